// round 3
// baseline (speedup 1.0000x reference)
#include <cuda_runtime.h>
#include <cuda_bf16.h>
#include <cstdint>

// Problem constants
#define NB   8
#define LQ   2048
#define LK   2048
#define DD   128
// Tiling
#define BQ   128
#define BK   64
#define THREADS 256            // 8 warps, each owns 16 Q rows
#define NKT  (LK / BK)         // 32 k-tiles
// Shared memory strides (padded for ldmatrix bank-conflict avoidance)
#define QK_STRIDE 136          // 128 halfs + 8 pad  (16B pad -> distinct 16B banks)
#define SC_STRIDE 68           // 64 floats + 4 pad  (keeps float4 16B alignment)
#define LOG2E 1.4426950408889634f

#define SMEM_BYTES ( (2*BQ*QK_STRIDE + 4*BK*QK_STRIDE) * 2 /*bf16*/ \
                   + BQ*SC_STRIDE*4 /*scale fp32*/ )          // = 174080 B

__device__ __forceinline__ uint32_t smem_u32(const void* p) {
    return (uint32_t)__cvta_generic_to_shared(p);
}
__device__ __forceinline__ void ldsm_x4(uint32_t& r0, uint32_t& r1, uint32_t& r2, uint32_t& r3, uint32_t a) {
    asm volatile("ldmatrix.sync.aligned.m8n8.x4.shared.b16 {%0,%1,%2,%3}, [%4];\n"
        : "=r"(r0), "=r"(r1), "=r"(r2), "=r"(r3) : "r"(a));
}
__device__ __forceinline__ void ldsm_x2(uint32_t& r0, uint32_t& r1, uint32_t a) {
    asm volatile("ldmatrix.sync.aligned.m8n8.x2.shared.b16 {%0,%1}, [%2];\n"
        : "=r"(r0), "=r"(r1) : "r"(a));
}
__device__ __forceinline__ void ldsm_x2_t(uint32_t& r0, uint32_t& r1, uint32_t a) {
    asm volatile("ldmatrix.sync.aligned.m8n8.x2.trans.shared.b16 {%0,%1}, [%2];\n"
        : "=r"(r0), "=r"(r1) : "r"(a));
}
__device__ __forceinline__ void mma_bf16(float* c,
    uint32_t a0, uint32_t a1, uint32_t a2, uint32_t a3, uint32_t b0, uint32_t b1) {
    asm volatile(
      "mma.sync.aligned.m16n8k16.row.col.f32.bf16.bf16.f32 "
      "{%0,%1,%2,%3}, {%4,%5,%6,%7}, {%8,%9}, {%0,%1,%2,%3};\n"
      : "+f"(c[0]), "+f"(c[1]), "+f"(c[2]), "+f"(c[3])
      : "r"(a0), "r"(a1), "r"(a2), "r"(a3), "r"(b0), "r"(b1));
}
// pack two fp32 -> bf16x2 register (lo half = x, hi half = y), round-to-nearest
__device__ __forceinline__ uint32_t packbf(float x, float y) {
    uint32_t r;
    asm("cvt.rn.bf16x2.f32 %0, %1, %2;\n" : "=r"(r) : "f"(y), "f"(x));
    return r;
}

// split fp32 quad into bf16 hi + bf16 lo residual, store as 2x bf16x2 each
__device__ __forceinline__ void split_store4(float4 x, __nv_bfloat16* hi, __nv_bfloat16* lo) {
    __nv_bfloat16 h0 = __float2bfloat16(x.x);
    __nv_bfloat16 h1 = __float2bfloat16(x.y);
    __nv_bfloat16 h2 = __float2bfloat16(x.z);
    __nv_bfloat16 h3 = __float2bfloat16(x.w);
    __nv_bfloat162 hA; hA.x = h0; hA.y = h1;
    __nv_bfloat162 hB; hB.x = h2; hB.y = h3;
    *(__nv_bfloat162*)(hi)     = hA;
    *(__nv_bfloat162*)(hi + 2) = hB;
    __nv_bfloat162 lA, lB;
    lA.x = __float2bfloat16(x.x - __bfloat162float(h0));
    lA.y = __float2bfloat16(x.y - __bfloat162float(h1));
    lB.x = __float2bfloat16(x.z - __bfloat162float(h2));
    lB.y = __float2bfloat16(x.w - __bfloat162float(h3));
    *(__nv_bfloat162*)(lo)     = lA;
    *(__nv_bfloat162*)(lo + 2) = lB;
}

__global__ void __launch_bounds__(THREADS, 1)
Model_48876727828871_kernel(const float* __restrict__ Q, const float* __restrict__ K,
                            const float* __restrict__ V, const float* __restrict__ SF,
                            float* __restrict__ O) {
    extern __shared__ char smem_raw[];
    __nv_bfloat16* q_hi = (__nv_bfloat16*)smem_raw;
    __nv_bfloat16* q_lo = q_hi + BQ * QK_STRIDE;
    __nv_bfloat16* k_hi = q_lo + BQ * QK_STRIDE;
    __nv_bfloat16* k_lo = k_hi + BK * QK_STRIDE;
    __nv_bfloat16* v_hi = k_lo + BK * QK_STRIDE;
    __nv_bfloat16* v_lo = v_hi + BK * QK_STRIDE;
    float*         sc   = (float*)(v_lo + BK * QK_STRIDE);

    const int tid  = threadIdx.x;
    const int lane = tid & 31;
    const int w    = tid >> 5;          // warp id 0..7
    const int qb   = blockIdx.x;        // q tile
    const int b    = blockIdx.y;        // batch

    const size_t q_base  = ((size_t)b * LQ + (size_t)qb * BQ) * DD;
    const size_t kv_base = (size_t)b * LK * DD;
    const size_t sf_base = ((size_t)b * LQ + (size_t)qb * BQ) * LK;

    // ---- load + split Q tile (once) ----
    #pragma unroll 4
    for (int i = tid; i < BQ * (DD / 4); i += THREADS) {
        int r  = i >> 5;                // DD/4 = 32 float4 per row
        int c4 = (i & 31) << 2;
        float4 x = *(const float4*)(Q + q_base + (size_t)r * DD + c4);
        split_store4(x, q_hi + r * QK_STRIDE + c4, q_lo + r * QK_STRIDE + c4);
    }
    __syncthreads();

    // ---- per-thread accumulators ----
    float o[16][4];
    #pragma unroll
    for (int n = 0; n < 16; ++n) { o[n][0]=0.f; o[n][1]=0.f; o[n][2]=0.f; o[n][3]=0.f; }
    float m0 = -1e30f, m1 = -1e30f, l0 = 0.f, l1 = 0.f;

    const int wr = w * 16;              // warp's Q-row base within tile
    const int g  = lane >> 2;           // row within 8-group
    const int qr = lane & 3;            // quad index (column pair)
    const int la = lane & 15;

    for (int kt = 0; kt < NKT; ++kt) {
        // ---- load + split K,V tile; load scale tile ----
        const float* Kp = K + kv_base + (size_t)kt * BK * DD;
        const float* Vp = V + kv_base + (size_t)kt * BK * DD;
        #pragma unroll 2
        for (int i = tid; i < BK * (DD / 4); i += THREADS) {
            int r  = i >> 5;
            int c4 = (i & 31) << 2;
            float4 xk = *(const float4*)(Kp + (size_t)r * DD + c4);
            split_store4(xk, k_hi + r * QK_STRIDE + c4, k_lo + r * QK_STRIDE + c4);
            float4 xv = *(const float4*)(Vp + (size_t)r * DD + c4);
            split_store4(xv, v_hi + r * QK_STRIDE + c4, v_lo + r * QK_STRIDE + c4);
        }
        #pragma unroll 2
        for (int i = tid; i < BQ * (BK / 4); i += THREADS) {
            int r  = i >> 4;            // BK/4 = 16 float4 per row
            int c4 = (i & 15) << 2;
            float4 x = *(const float4*)(SF + sf_base + (size_t)r * LK + (size_t)kt * BK + c4);
            *(float4*)&sc[r * SC_STRIDE + c4] = x;
        }
        __syncthreads();

        // ---- S = Q K^T with bf16x3 split ----
        float cfr[8][4];
        #pragma unroll
        for (int n = 0; n < 8; ++n) { cfr[n][0]=0.f; cfr[n][1]=0.f; cfr[n][2]=0.f; cfr[n][3]=0.f; }

        const __nv_bfloat16* qsel[3] = { q_hi, q_hi, q_lo };
        const __nv_bfloat16* ksel[3] = { k_hi, k_lo, k_hi };
        #pragma unroll
        for (int s = 0; s < 3; ++s) {
            const __nv_bfloat16* qs = qsel[s];
            const __nv_bfloat16* ks = ksel[s];
            #pragma unroll
            for (int kk = 0; kk < 8; ++kk) {
                const int k0 = kk * 16;
                uint32_t a0, a1, a2, a3;
                ldsm_x4(a0, a1, a2, a3,
                        smem_u32(qs + (wr + (lane & 15)) * QK_STRIDE + k0 + (lane >> 4) * 8));
                #pragma unroll
                for (int n = 0; n < 8; ++n) {
                    uint32_t b0, b1;
                    ldsm_x2(b0, b1,
                            smem_u32(ks + (n * 8 + (la & 7)) * QK_STRIDE + k0 + (la >> 3) * 8));
                    mma_bf16(cfr[n], a0, a1, a2, a3, b0, b1);
                }
            }
        }

        // ---- elementwise scale + online softmax ----
        const int r0 = wr + g, r1 = r0 + 8;
        float mx0 = -1e30f, mx1 = -1e30f;
        #pragma unroll
        for (int n = 0; n < 8; ++n) {
            float2 s0 = *(float2*)&sc[r0 * SC_STRIDE + n * 8 + qr * 2];
            float2 s1 = *(float2*)&sc[r1 * SC_STRIDE + n * 8 + qr * 2];
            cfr[n][0] *= s0.x; cfr[n][1] *= s0.y;
            cfr[n][2] *= s1.x; cfr[n][3] *= s1.y;
            mx0 = fmaxf(mx0, fmaxf(cfr[n][0], cfr[n][1]));
            mx1 = fmaxf(mx1, fmaxf(cfr[n][2], cfr[n][3]));
        }
        mx0 = fmaxf(mx0, __shfl_xor_sync(0xffffffffu, mx0, 1));
        mx0 = fmaxf(mx0, __shfl_xor_sync(0xffffffffu, mx0, 2));
        mx1 = fmaxf(mx1, __shfl_xor_sync(0xffffffffu, mx1, 1));
        mx1 = fmaxf(mx1, __shfl_xor_sync(0xffffffffu, mx1, 2));

        const float mn0 = fmaxf(m0, mx0), mn1 = fmaxf(m1, mx1);
        const float al0 = exp2f((m0 - mn0) * LOG2E);
        const float al1 = exp2f((m1 - mn1) * LOG2E);
        m0 = mn0; m1 = mn1;

        float rs0 = 0.f, rs1 = 0.f;
        #pragma unroll
        for (int n = 0; n < 8; ++n) {
            cfr[n][0] = exp2f((cfr[n][0] - m0) * LOG2E);
            cfr[n][1] = exp2f((cfr[n][1] - m0) * LOG2E);
            cfr[n][2] = exp2f((cfr[n][2] - m1) * LOG2E);
            cfr[n][3] = exp2f((cfr[n][3] - m1) * LOG2E);
            rs0 += cfr[n][0] + cfr[n][1];
            rs1 += cfr[n][2] + cfr[n][3];
        }
        rs0 += __shfl_xor_sync(0xffffffffu, rs0, 1);
        rs0 += __shfl_xor_sync(0xffffffffu, rs0, 2);
        rs1 += __shfl_xor_sync(0xffffffffu, rs1, 1);
        rs1 += __shfl_xor_sync(0xffffffffu, rs1, 2);
        l0 = l0 * al0 + rs0;
        l1 = l1 * al1 + rs1;

        #pragma unroll
        for (int n = 0; n < 16; ++n) {
            o[n][0] *= al0; o[n][1] *= al0;
            o[n][2] *= al1; o[n][3] *= al1;
        }

        // ---- O += P V with bf16x3 split (P stays in registers) ----
        #pragma unroll
        for (int j = 0; j < 4; ++j) {
            float ph[8] = { cfr[2*j][0], cfr[2*j][1], cfr[2*j][2], cfr[2*j][3],
                            cfr[2*j+1][0], cfr[2*j+1][1], cfr[2*j+1][2], cfr[2*j+1][3] };
            float pl[8];
            #pragma unroll
            for (int t = 0; t < 8; ++t)
                pl[t] = ph[t] - __bfloat162float(__float2bfloat16(ph[t]));
            uint32_t ah[4] = { packbf(ph[0], ph[1]), packbf(ph[2], ph[3]),
                               packbf(ph[4], ph[5]), packbf(ph[6], ph[7]) };
            uint32_t al_[4] = { packbf(pl[0], pl[1]), packbf(pl[2], pl[3]),
                                packbf(pl[4], pl[5]), packbf(pl[6], pl[7]) };
            const int k0 = j * 16;
            #pragma unroll
            for (int n = 0; n < 16; ++n) {
                uint32_t bh0, bh1, bl0, bl1;
                ldsm_x2_t(bh0, bh1, smem_u32(v_hi + (k0 + la) * QK_STRIDE + n * 8));
                ldsm_x2_t(bl0, bl1, smem_u32(v_lo + (k0 + la) * QK_STRIDE + n * 8));
                mma_bf16(o[n], ah[0], ah[1], ah[2], ah[3], bh0, bh1);
                mma_bf16(o[n], ah[0], ah[1], ah[2], ah[3], bl0, bl1);
                mma_bf16(o[n], al_[0], al_[1], al_[2], al_[3], bh0, bh1);
            }
        }
        __syncthreads();
    }

    // ---- epilogue: normalize and store ----
    const float inv0 = 1.f / l0;
    const float inv1 = 1.f / l1;
    const size_t ob = ((size_t)b * LQ + (size_t)qb * BQ) * DD;
    const int r0 = wr + g, r1 = r0 + 8;
    #pragma unroll
    for (int n = 0; n < 16; ++n) {
        const int col = n * 8 + qr * 2;
        float2 t0; t0.x = o[n][0] * inv0; t0.y = o[n][1] * inv0;
        *(float2*)(O + ob + (size_t)r0 * DD + col) = t0;
        float2 t1; t1.x = o[n][2] * inv1; t1.y = o[n][3] * inv1;
        *(float2*)(O + ob + (size_t)r1 * DD + col) = t1;
    }
}

extern "C" void kernel_launch(void* const* d_in, const int* in_sizes, int n_in,
                              void* d_out, int out_size) {
    (void)in_sizes; (void)n_in; (void)out_size;
    const float* q  = (const float*)d_in[0];
    const float* k  = (const float*)d_in[1];
    const float* v  = (const float*)d_in[2];
    const float* sf = (const float*)d_in[3];
    float* out = (float*)d_out;

    cudaFuncSetAttribute(Model_48876727828871_kernel,
                         cudaFuncAttributeMaxDynamicSharedMemorySize, SMEM_BYTES);
    dim3 grid(LQ / BQ, NB);
    Model_48876727828871_kernel<<<grid, THREADS, SMEM_BYTES>>>(q, k, v, sf, out);
}

// round 6
// speedup vs baseline: 1.8769x; 1.8769x over previous
#include <cuda_runtime.h>
#include <cuda_bf16.h>
#include <cstdint>

// Problem constants
#define NB   8
#define LQ   2048
#define LK   2048
#define DD   128
// Tiling
#define BQ   128
#define BK   64
#define THREADS 256            // 8 warps, each owns 16 Q rows
#define NKT  (LK / BK)         // 32 k-tiles
#define SC_STRIDE 68           // 64 floats + 4 pad (272B rows: 16B-aligned, bank-spread)
#define LOG2E 1.4426950408889634f

// Shared memory layout (bytes). Q/K/V tiles are XOR-swizzled, stride 128 halves (256B/row).
#define SM_QHI   0              // 128 x 128 bf16 = 32768
#define SM_QLO   32768
#define SM_STG   65536          // two stages of {khi,klo,vhi,vlo}, 64x128 bf16 each
#define STG_SZ   65536
#define STG_KLO  16384
#define STG_VHI  32768
#define STG_VLO  49152
#define SM_SC    196608         // 128 x 68 fp32 = 34816
#define SMEM_BYTES 231424       // <= 232448 (227 KB max dynamic smem / block)

// Prepass scratch: K,V pre-split into bf16 hi/lo (16 MB total)
__device__ __nv_bfloat16 g_khi[(size_t)NB * LK * DD];
__device__ __nv_bfloat16 g_klo[(size_t)NB * LK * DD];
__device__ __nv_bfloat16 g_vhi[(size_t)NB * LK * DD];
__device__ __nv_bfloat16 g_vlo[(size_t)NB * LK * DD];

__device__ __forceinline__ uint32_t smem_u32(const void* p) {
    return (uint32_t)__cvta_generic_to_shared(p);
}
// XOR swizzle: row-major tile, 256B rows, 16B chunks; low-3 chunk bits XOR row&7.
__device__ __forceinline__ uint32_t swzb(int row, int ch) {
    return (uint32_t)(row * 256 + ((((ch ^ row) & 7) | (ch & 8)) << 4));
}
__device__ __forceinline__ void ldsm_x4(uint32_t& r0, uint32_t& r1, uint32_t& r2, uint32_t& r3, uint32_t a) {
    asm volatile("ldmatrix.sync.aligned.m8n8.x4.shared.b16 {%0,%1,%2,%3}, [%4];\n"
        : "=r"(r0), "=r"(r1), "=r"(r2), "=r"(r3) : "r"(a));
}
__device__ __forceinline__ void ldsm_x4t(uint32_t& r0, uint32_t& r1, uint32_t& r2, uint32_t& r3, uint32_t a) {
    asm volatile("ldmatrix.sync.aligned.m8n8.x4.trans.shared.b16 {%0,%1,%2,%3}, [%4];\n"
        : "=r"(r0), "=r"(r1), "=r"(r2), "=r"(r3) : "r"(a));
}
__device__ __forceinline__ void mma_bf16(float* c,
    uint32_t a0, uint32_t a1, uint32_t a2, uint32_t a3, uint32_t b0, uint32_t b1) {
    asm volatile(
      "mma.sync.aligned.m16n8k16.row.col.f32.bf16.bf16.f32 "
      "{%0,%1,%2,%3}, {%4,%5,%6,%7}, {%8,%9}, {%0,%1,%2,%3};\n"
      : "+f"(c[0]), "+f"(c[1]), "+f"(c[2]), "+f"(c[3])
      : "r"(a0), "r"(a1), "r"(a2), "r"(a3), "r"(b0), "r"(b1));
}
__device__ __forceinline__ uint32_t packbf(float x, float y) {
    uint32_t r;
    asm("cvt.rn.bf16x2.f32 %0, %1, %2;\n" : "=r"(r) : "f"(y), "f"(x));
    return r;
}
__device__ __forceinline__ void split_store4(float4 x, __nv_bfloat16* hi, __nv_bfloat16* lo) {
    __nv_bfloat16 h0 = __float2bfloat16(x.x);
    __nv_bfloat16 h1 = __float2bfloat16(x.y);
    __nv_bfloat16 h2 = __float2bfloat16(x.z);
    __nv_bfloat16 h3 = __float2bfloat16(x.w);
    __nv_bfloat162 hA; hA.x = h0; hA.y = h1;
    __nv_bfloat162 hB; hB.x = h2; hB.y = h3;
    *(__nv_bfloat162*)(hi)     = hA;
    *(__nv_bfloat162*)(hi + 2) = hB;
    __nv_bfloat162 lA, lB;
    lA.x = __float2bfloat16(x.x - __bfloat162float(h0));
    lA.y = __float2bfloat16(x.y - __bfloat162float(h1));
    lB.x = __float2bfloat16(x.z - __bfloat162float(h2));
    lB.y = __float2bfloat16(x.w - __bfloat162float(h3));
    *(__nv_bfloat162*)(lo)     = lA;
    *(__nv_bfloat162*)(lo + 2) = lB;
}

#define CP16(dst, src) asm volatile("cp.async.cg.shared.global [%0], [%1], 16;\n" :: "r"(dst), "l"(src))
#define CPCOMMIT()     asm volatile("cp.async.commit_group;\n" ::: "memory")
#define CPWAIT(n)      asm volatile("cp.async.wait_group %0;\n" :: "n"(n) : "memory")

// ---- prepass: split K,V fp32 -> bf16 hi/lo scratch ----
__global__ void split_kv_prepass(const float4* __restrict__ K, const float4* __restrict__ V) {
    const int n4 = NB * LK * DD / 4;
    for (int i = blockIdx.x * blockDim.x + threadIdx.x; i < 2 * n4; i += gridDim.x * blockDim.x) {
        const bool isv = i >= n4;
        const int j = isv ? i - n4 : i;
        float4 x = isv ? V[j] : K[j];
        __nv_bfloat16* hp = (isv ? g_vhi : g_khi) + (size_t)j * 4;
        __nv_bfloat16* lp = (isv ? g_vlo : g_klo) + (size_t)j * 4;
        split_store4(x, hp, lp);
    }
}

// Issue cp.async for one K/V tile (all 4 hi/lo arrays) into a stage buffer.
__device__ __forceinline__ void issue_kv_tile(uint32_t stage_b,
    const __nv_bfloat16* __restrict__ khi, const __nv_bfloat16* __restrict__ klo,
    const __nv_bfloat16* __restrict__ vhi, const __nv_bfloat16* __restrict__ vlo, int tid) {
    const __nv_bfloat16* srcs[4] = { khi, klo, vhi, vlo };
    #pragma unroll
    for (int a = 0; a < 4; ++a) {
        const __nv_bfloat16* s = srcs[a];
        const uint32_t db = stage_b + a * 16384;
        #pragma unroll
        for (int k = 0; k < 4; ++k) {
            int i = tid + k * THREADS;          // 0..1023 chunks (64 rows x 16)
            int row = i >> 4, ch = i & 15;
            CP16(db + swzb(row, ch), s + (size_t)row * DD + ch * 8);
        }
    }
}
__device__ __forceinline__ void issue_sc_tile(uint32_t sc_b, const float* __restrict__ sf, int tid) {
    #pragma unroll
    for (int k = 0; k < 8; ++k) {
        int i = tid + k * THREADS;              // 0..2047 chunks (128 rows x 16)
        int row = i >> 4, ch = i & 15;
        CP16(sc_b + row * (SC_STRIDE * 4) + ch * 16, sf + (size_t)row * LK + ch * 4);
    }
}

__global__ void __launch_bounds__(THREADS, 1)
Model_48876727828871_kernel(const float* __restrict__ Q, const float* __restrict__ SF,
                            float* __restrict__ O) {
    extern __shared__ char smem_raw[];
    const uint32_t smem_b = smem_u32(smem_raw);
    float* sc = (float*)(smem_raw + SM_SC);

    const int tid  = threadIdx.x;
    const int lane = tid & 31;
    const int w    = tid >> 5;
    const int qb   = blockIdx.x;
    const int b    = blockIdx.y;

    const size_t q_base  = ((size_t)b * LQ + (size_t)qb * BQ) * DD;
    const size_t kv_base = (size_t)b * LK * DD;
    const size_t sf_base = ((size_t)b * LQ + (size_t)qb * BQ) * LK;

    // ---- prologue: start async loads for tile 0, then load+split Q ----
    issue_kv_tile(smem_b + SM_STG, g_khi + kv_base, g_klo + kv_base,
                  g_vhi + kv_base, g_vlo + kv_base, tid);
    CPCOMMIT();
    issue_sc_tile(smem_b + SM_SC, SF + sf_base, tid);
    CPCOMMIT();

    #pragma unroll 4
    for (int i = tid; i < BQ * (DD / 4); i += THREADS) {
        int r  = i >> 5;
        int c4 = (i & 31) << 2;
        float4 x = *(const float4*)(Q + q_base + (size_t)r * DD + c4);
        uint32_t off = swzb(r, c4 >> 3) + (c4 & 4) * 2;
        split_store4(x, (__nv_bfloat16*)(smem_raw + SM_QHI + off),
                        (__nv_bfloat16*)(smem_raw + SM_QLO + off));
    }
    CPWAIT(1);                    // K/V tile 0 resident (sc may still be in flight)
    __syncthreads();

    // ---- accumulators ----
    float o[16][4];
    #pragma unroll
    for (int n = 0; n < 16; ++n) { o[n][0]=0.f; o[n][1]=0.f; o[n][2]=0.f; o[n][3]=0.f; }
    float m0 = -1e30f, m1 = -1e30f, l0 = 0.f, l1 = 0.f;

    const int wr = w * 16;
    const int g  = lane >> 2;
    const int qr = lane & 3;
    const uint32_t qh_b = smem_b + SM_QHI;
    const uint32_t ql_b = smem_b + SM_QLO;

    for (int kt = 0; kt < NKT; ++kt) {
        const int buf = kt & 1;
        const uint32_t stage = smem_b + SM_STG + buf * STG_SZ;

        // prefetch next K/V tile into the other stage
        if (kt + 1 < NKT) {
            const size_t off = kv_base + (size_t)(kt + 1) * BK * DD;
            issue_kv_tile(smem_b + SM_STG + (buf ^ 1) * STG_SZ,
                          g_khi + off, g_klo + off, g_vhi + off, g_vlo + off, tid);
        }
        CPCOMMIT();

        // ---- S = Q K^T, bf16x3 split with fragment reuse ----
        float cfr[8][4];
        #pragma unroll
        for (int n = 0; n < 8; ++n) { cfr[n][0]=0.f; cfr[n][1]=0.f; cfr[n][2]=0.f; cfr[n][3]=0.f; }
        {
            const uint32_t kh_b = stage, kl_b = stage + STG_KLO;
            #pragma unroll
            for (int kk = 0; kk < 8; ++kk) {
                const int k0 = kk * 16;
                const int arow = wr + (lane & 15);
                const int ach  = (k0 >> 3) + (lane >> 4);
                const uint32_t aoff = swzb(arow, ach);
                uint32_t ah0,ah1,ah2,ah3, al0,al1,al2,al3;
                ldsm_x4(ah0,ah1,ah2,ah3, qh_b + aoff);
                ldsm_x4(al0,al1,al2,al3, ql_b + aoff);
                #pragma unroll
                for (int np = 0; np < 4; ++np) {
                    const int brow = (2*np + ((lane >> 4) & 1)) * 8 + (lane & 7);
                    const int bch  = (k0 >> 3) + ((lane >> 3) & 1);
                    const uint32_t boff = swzb(brow, bch);
                    uint32_t bh0,bh1,bh2,bh3, bl0,bl1,bl2,bl3;
                    ldsm_x4(bh0,bh1,bh2,bh3, kh_b + boff);
                    ldsm_x4(bl0,bl1,bl2,bl3, kl_b + boff);
                    mma_bf16(cfr[2*np],   ah0,ah1,ah2,ah3, bh0,bh1);
                    mma_bf16(cfr[2*np+1], ah0,ah1,ah2,ah3, bh2,bh3);
                    mma_bf16(cfr[2*np],   ah0,ah1,ah2,ah3, bl0,bl1);
                    mma_bf16(cfr[2*np+1], ah0,ah1,ah2,ah3, bl2,bl3);
                    mma_bf16(cfr[2*np],   al0,al1,al2,al3, bh0,bh1);
                    mma_bf16(cfr[2*np+1], al0,al1,al2,al3, bh2,bh3);
                }
            }
        }

        // scale tile for this kt must be resident
        CPWAIT(1);
        __syncthreads();

        // ---- elementwise scale + online softmax ----
        const int r0 = wr + g, r1 = r0 + 8;
        float mx0 = -1e30f, mx1 = -1e30f;
        #pragma unroll
        for (int n = 0; n < 8; ++n) {
            float2 s0 = *(float2*)&sc[r0 * SC_STRIDE + n * 8 + qr * 2];
            float2 s1 = *(float2*)&sc[r1 * SC_STRIDE + n * 8 + qr * 2];
            cfr[n][0] *= s0.x; cfr[n][1] *= s0.y;
            cfr[n][2] *= s1.x; cfr[n][3] *= s1.y;
            mx0 = fmaxf(mx0, fmaxf(cfr[n][0], cfr[n][1]));
            mx1 = fmaxf(mx1, fmaxf(cfr[n][2], cfr[n][3]));
        }
        mx0 = fmaxf(mx0, __shfl_xor_sync(0xffffffffu, mx0, 1));
        mx0 = fmaxf(mx0, __shfl_xor_sync(0xffffffffu, mx0, 2));
        mx1 = fmaxf(mx1, __shfl_xor_sync(0xffffffffu, mx1, 1));
        mx1 = fmaxf(mx1, __shfl_xor_sync(0xffffffffu, mx1, 2));

        const float mn0 = fmaxf(m0, mx0), mn1 = fmaxf(m1, mx1);
        const float al0 = exp2f((m0 - mn0) * LOG2E);
        const float al1 = exp2f((m1 - mn1) * LOG2E);
        m0 = mn0; m1 = mn1;

        float rs0 = 0.f, rs1 = 0.f;
        #pragma unroll
        for (int n = 0; n < 8; ++n) {
            cfr[n][0] = exp2f((cfr[n][0] - m0) * LOG2E);
            cfr[n][1] = exp2f((cfr[n][1] - m0) * LOG2E);
            cfr[n][2] = exp2f((cfr[n][2] - m1) * LOG2E);
            cfr[n][3] = exp2f((cfr[n][3] - m1) * LOG2E);
            rs0 += cfr[n][0] + cfr[n][1];
            rs1 += cfr[n][2] + cfr[n][3];
        }
        rs0 += __shfl_xor_sync(0xffffffffu, rs0, 1);
        rs0 += __shfl_xor_sync(0xffffffffu, rs0, 2);
        rs1 += __shfl_xor_sync(0xffffffffu, rs1, 1);
        rs1 += __shfl_xor_sync(0xffffffffu, rs1, 2);
        l0 = l0 * al0 + rs0;
        l1 = l1 * al1 + rs1;

        #pragma unroll
        for (int n = 0; n < 16; ++n) {
            o[n][0] *= al0; o[n][1] *= al0;
            o[n][2] *= al1; o[n][3] *= al1;
        }

        // all sc reads done -> safe to refill sc for kt+1 (deadline: next softmax)
        __syncthreads();
        if (kt + 1 < NKT)
            issue_sc_tile(smem_b + SM_SC, SF + sf_base + (size_t)(kt + 1) * BK, tid);
        CPCOMMIT();

        // ---- O += P V, bf16x3 split, x4 transposed V loads ----
        {
            const uint32_t vh_b = stage + STG_VHI, vl_b = stage + STG_VLO;
            #pragma unroll
            for (int j = 0; j < 4; ++j) {
                float ph[8] = { cfr[2*j][0], cfr[2*j][1], cfr[2*j][2], cfr[2*j][3],
                                cfr[2*j+1][0], cfr[2*j+1][1], cfr[2*j+1][2], cfr[2*j+1][3] };
                float pl[8];
                #pragma unroll
                for (int t = 0; t < 8; ++t)
                    pl[t] = ph[t] - __bfloat162float(__float2bfloat16(ph[t]));
                uint32_t ah[4] = { packbf(ph[0], ph[1]), packbf(ph[2], ph[3]),
                                   packbf(ph[4], ph[5]), packbf(ph[6], ph[7]) };
                uint32_t al_[4] = { packbf(pl[0], pl[1]), packbf(pl[2], pl[3]),
                                    packbf(pl[4], pl[5]), packbf(pl[6], pl[7]) };
                const int k0 = j * 16;
                const int vrow = k0 + ((lane >> 3) & 1) * 8 + (lane & 7);
                #pragma unroll
                for (int np = 0; np < 8; ++np) {
                    const int vch = 2 * np + (lane >> 4);
                    const uint32_t voff = swzb(vrow, vch);
                    uint32_t bh0,bh1,bh2,bh3, bl0,bl1,bl2,bl3;
                    ldsm_x4t(bh0,bh1,bh2,bh3, vh_b + voff);
                    ldsm_x4t(bl0,bl1,bl2,bl3, vl_b + voff);
                    mma_bf16(o[2*np],   ah[0],ah[1],ah[2],ah[3], bh0,bh1);
                    mma_bf16(o[2*np+1], ah[0],ah[1],ah[2],ah[3], bh2,bh3);
                    mma_bf16(o[2*np],   ah[0],ah[1],ah[2],ah[3], bl0,bl1);
                    mma_bf16(o[2*np+1], ah[0],ah[1],ah[2],ah[3], bl2,bl3);
                    mma_bf16(o[2*np],   al_[0],al_[1],al_[2],al_[3], bh0,bh1);
                    mma_bf16(o[2*np+1], al_[0],al_[1],al_[2],al_[3], bh2,bh3);
                }
            }
        }

        // next K/V tile resident before flipping buffers
        CPWAIT(1);
        __syncthreads();
    }

    // ---- epilogue ----
    const float inv0 = 1.f / l0;
    const float inv1 = 1.f / l1;
    const size_t ob = ((size_t)b * LQ + (size_t)qb * BQ) * DD;
    const int r0 = wr + g, r1 = r0 + 8;
    #pragma unroll
    for (int n = 0; n < 16; ++n) {
        const int col = n * 8 + qr * 2;
        float2 t0; t0.x = o[n][0] * inv0; t0.y = o[n][1] * inv0;
        *(float2*)(O + ob + (size_t)r0 * DD + col) = t0;
        float2 t1; t1.x = o[n][2] * inv1; t1.y = o[n][3] * inv1;
        *(float2*)(O + ob + (size_t)r1 * DD + col) = t1;
    }
}

extern "C" void kernel_launch(void* const* d_in, const int* in_sizes, int n_in,
                              void* d_out, int out_size) {
    (void)in_sizes; (void)n_in; (void)out_size;
    const float* q  = (const float*)d_in[0];
    const float* k  = (const float*)d_in[1];
    const float* v  = (const float*)d_in[2];
    const float* sf = (const float*)d_in[3];
    float* out = (float*)d_out;

    split_kv_prepass<<<2048, 256>>>((const float4*)k, (const float4*)v);

    cudaFuncSetAttribute(Model_48876727828871_kernel,
                         cudaFuncAttributeMaxDynamicSharedMemorySize, SMEM_BYTES);
    dim3 grid(LQ / BQ, NB);
    Model_48876727828871_kernel<<<grid, THREADS, SMEM_BYTES>>>(q, sf, out);
}

// round 7
// speedup vs baseline: 1.8858x; 1.0047x over previous
#include <cuda_runtime.h>
#include <cuda_bf16.h>
#include <cstdint>

// Problem constants
#define NB   8
#define LQ   2048
#define LK   2048
#define DD   128
// Tiling
#define BQ   128
#define BK   64
#define THREADS 256            // 8 warps, each owns 16 Q rows
#define NKT  (LK / BK)         // 32 k-tiles
#define SC_STRIDE 68           // 64 floats + 4 pad (272B rows: 16B-aligned, bank-spread)
#define LOG2E 1.4426950408889634f

// Shared memory layout (bytes). Q/K/V tiles are XOR-swizzled, stride 128 halves (256B/row).
#define SM_QHI   0              // 128 x 128 bf16 = 32768
#define SM_QLO   32768
#define SM_STG   65536          // two stages of {khi,klo,vhi,vlo}, 64x128 bf16 each
#define STG_SZ   65536
#define STG_KLO  16384
#define STG_VHI  32768
#define STG_VLO  49152
#define SM_SC    196608         // 128 x 68 fp32 = 34816
#define SMEM_BYTES 231424       // <= 232448 (227 KB max dynamic smem / block)

// Prepass scratch: K,V pre-split into bf16 hi/lo (16 MB total)
__device__ __nv_bfloat16 g_khi[(size_t)NB * LK * DD];
__device__ __nv_bfloat16 g_klo[(size_t)NB * LK * DD];
__device__ __nv_bfloat16 g_vhi[(size_t)NB * LK * DD];
__device__ __nv_bfloat16 g_vlo[(size_t)NB * LK * DD];

__device__ __forceinline__ uint32_t smem_u32(const void* p) {
    return (uint32_t)__cvta_generic_to_shared(p);
}
// XOR swizzle: row-major tile, 256B rows, 16B chunks; low-3 chunk bits XOR row&7.
__device__ __forceinline__ uint32_t swzb(int row, int ch) {
    return (uint32_t)(row * 256 + ((((ch ^ row) & 7) | (ch & 8)) << 4));
}
__device__ __forceinline__ void ldsm_x4(uint32_t& r0, uint32_t& r1, uint32_t& r2, uint32_t& r3, uint32_t a) {
    asm volatile("ldmatrix.sync.aligned.m8n8.x4.shared.b16 {%0,%1,%2,%3}, [%4];\n"
        : "=r"(r0), "=r"(r1), "=r"(r2), "=r"(r3) : "r"(a));
}
__device__ __forceinline__ void ldsm_x4t(uint32_t& r0, uint32_t& r1, uint32_t& r2, uint32_t& r3, uint32_t a) {
    asm volatile("ldmatrix.sync.aligned.m8n8.x4.trans.shared.b16 {%0,%1,%2,%3}, [%4];\n"
        : "=r"(r0), "=r"(r1), "=r"(r2), "=r"(r3) : "r"(a));
}
__device__ __forceinline__ void mma_bf16(float* c,
    uint32_t a0, uint32_t a1, uint32_t a2, uint32_t a3, uint32_t b0, uint32_t b1) {
    asm volatile(
      "mma.sync.aligned.m16n8k16.row.col.f32.bf16.bf16.f32 "
      "{%0,%1,%2,%3}, {%4,%5,%6,%7}, {%8,%9}, {%0,%1,%2,%3};\n"
      : "+f"(c[0]), "+f"(c[1]), "+f"(c[2]), "+f"(c[3])
      : "r"(a0), "r"(a1), "r"(a2), "r"(a3), "r"(b0), "r"(b1));
}
__device__ __forceinline__ uint32_t packbf(float x, float y) {
    uint32_t r;
    asm("cvt.rn.bf16x2.f32 %0, %1, %2;\n" : "=r"(r) : "f"(y), "f"(x));
    return r;
}
__device__ __forceinline__ void split_store4(float4 x, __nv_bfloat16* hi, __nv_bfloat16* lo) {
    __nv_bfloat16 h0 = __float2bfloat16(x.x);
    __nv_bfloat16 h1 = __float2bfloat16(x.y);
    __nv_bfloat16 h2 = __float2bfloat16(x.z);
    __nv_bfloat16 h3 = __float2bfloat16(x.w);
    __nv_bfloat162 hA; hA.x = h0; hA.y = h1;
    __nv_bfloat162 hB; hB.x = h2; hB.y = h3;
    *(__nv_bfloat162*)(hi)     = hA;
    *(__nv_bfloat162*)(hi + 2) = hB;
    __nv_bfloat162 lA, lB;
    lA.x = __float2bfloat16(x.x - __bfloat162float(h0));
    lA.y = __float2bfloat16(x.y - __bfloat162float(h1));
    lB.x = __float2bfloat16(x.z - __bfloat162float(h2));
    lB.y = __float2bfloat16(x.w - __bfloat162float(h3));
    *(__nv_bfloat162*)(lo)     = lA;
    *(__nv_bfloat162*)(lo + 2) = lB;
}

#define CP16(dst, src) asm volatile("cp.async.cg.shared.global [%0], [%1], 16;\n" :: "r"(dst), "l"(src))
#define CPCOMMIT()     asm volatile("cp.async.commit_group;\n" ::: "memory")
#define CPWAIT(n)      asm volatile("cp.async.wait_group %0;\n" :: "n"(n) : "memory")

// ---- prepass: split K,V fp32 -> bf16 hi/lo scratch ----
__global__ void split_kv_prepass(const float4* __restrict__ K, const float4* __restrict__ V) {
    const int n4 = NB * LK * DD / 4;
    for (int i = blockIdx.x * blockDim.x + threadIdx.x; i < 2 * n4; i += gridDim.x * blockDim.x) {
        const bool isv = i >= n4;
        const int j = isv ? i - n4 : i;
        float4 x = isv ? V[j] : K[j];
        __nv_bfloat16* hp = (isv ? g_vhi : g_khi) + (size_t)j * 4;
        __nv_bfloat16* lp = (isv ? g_vlo : g_klo) + (size_t)j * 4;
        split_store4(x, hp, lp);
    }
}

// Issue cp.async for one K/V tile (all 4 hi/lo arrays) into a stage buffer.
__device__ __forceinline__ void issue_kv_tile(uint32_t stage_b,
    const __nv_bfloat16* __restrict__ khi, const __nv_bfloat16* __restrict__ klo,
    const __nv_bfloat16* __restrict__ vhi, const __nv_bfloat16* __restrict__ vlo, int tid) {
    const __nv_bfloat16* srcs[4] = { khi, klo, vhi, vlo };
    #pragma unroll
    for (int a = 0; a < 4; ++a) {
        const __nv_bfloat16* s = srcs[a];
        const uint32_t db = stage_b + a * 16384;
        #pragma unroll
        for (int k = 0; k < 4; ++k) {
            int i = tid + k * THREADS;          // 0..1023 chunks (64 rows x 16)
            int row = i >> 4, ch = i & 15;
            CP16(db + swzb(row, ch), s + (size_t)row * DD + ch * 8);
        }
    }
}
__device__ __forceinline__ void issue_sc_tile(uint32_t sc_b, const float* __restrict__ sf, int tid) {
    #pragma unroll
    for (int k = 0; k < 8; ++k) {
        int i = tid + k * THREADS;              // 0..2047 chunks (128 rows x 16)
        int row = i >> 4, ch = i & 15;
        CP16(sc_b + row * (SC_STRIDE * 4) + ch * 16, sf + (size_t)row * LK + ch * 4);
    }
}

__global__ void __launch_bounds__(THREADS, 1)
Model_48876727828871_kernel(const float* __restrict__ Q, const float* __restrict__ SF,
                            float* __restrict__ O) {
    extern __shared__ char smem_raw[];
    const uint32_t smem_b = smem_u32(smem_raw);
    float* sc = (float*)(smem_raw + SM_SC);

    const int tid  = threadIdx.x;
    const int lane = tid & 31;
    const int w    = tid >> 5;
    const int qb   = blockIdx.x;
    const int b    = blockIdx.y;

    const size_t q_base  = ((size_t)b * LQ + (size_t)qb * BQ) * DD;
    const size_t kv_base = (size_t)b * LK * DD;
    const size_t sf_base = ((size_t)b * LQ + (size_t)qb * BQ) * LK;

    // ---- prologue: start async loads for tile 0, then load+split Q ----
    issue_kv_tile(smem_b + SM_STG, g_khi + kv_base, g_klo + kv_base,
                  g_vhi + kv_base, g_vlo + kv_base, tid);
    CPCOMMIT();
    issue_sc_tile(smem_b + SM_SC, SF + sf_base, tid);
    CPCOMMIT();

    #pragma unroll 4
    for (int i = tid; i < BQ * (DD / 4); i += THREADS) {
        int r  = i >> 5;
        int c4 = (i & 31) << 2;
        float4 x = *(const float4*)(Q + q_base + (size_t)r * DD + c4);
        uint32_t off = swzb(r, c4 >> 3) + (c4 & 4) * 2;
        split_store4(x, (__nv_bfloat16*)(smem_raw + SM_QHI + off),
                        (__nv_bfloat16*)(smem_raw + SM_QLO + off));
    }
    CPWAIT(1);                    // K/V tile 0 resident (sc may still be in flight)
    __syncthreads();

    // ---- accumulators ----
    float o[16][4];
    #pragma unroll
    for (int n = 0; n < 16; ++n) { o[n][0]=0.f; o[n][1]=0.f; o[n][2]=0.f; o[n][3]=0.f; }
    float m0 = -1e30f, m1 = -1e30f, l0 = 0.f, l1 = 0.f;

    const int wr = w * 16;
    const int g  = lane >> 2;
    const int qr = lane & 3;
    const uint32_t qh_b = smem_b + SM_QHI;
    const uint32_t ql_b = smem_b + SM_QLO;

    for (int kt = 0; kt < NKT; ++kt) {
        const int buf = kt & 1;
        const uint32_t stage = smem_b + SM_STG + buf * STG_SZ;

        // prefetch next K/V tile into the other stage
        if (kt + 1 < NKT) {
            const size_t off = kv_base + (size_t)(kt + 1) * BK * DD;
            issue_kv_tile(smem_b + SM_STG + (buf ^ 1) * STG_SZ,
                          g_khi + off, g_klo + off, g_vhi + off, g_vlo + off, tid);
        }
        CPCOMMIT();

        // ---- S = Q K^T, bf16x3 split with fragment reuse ----
        float cfr[8][4];
        #pragma unroll
        for (int n = 0; n < 8; ++n) { cfr[n][0]=0.f; cfr[n][1]=0.f; cfr[n][2]=0.f; cfr[n][3]=0.f; }
        {
            const uint32_t kh_b = stage, kl_b = stage + STG_KLO;
            #pragma unroll
            for (int kk = 0; kk < 8; ++kk) {
                const int k0 = kk * 16;
                const int arow = wr + (lane & 15);
                const int ach  = (k0 >> 3) + (lane >> 4);
                const uint32_t aoff = swzb(arow, ach);
                uint32_t ah0,ah1,ah2,ah3, al0,al1,al2,al3;
                ldsm_x4(ah0,ah1,ah2,ah3, qh_b + aoff);
                ldsm_x4(al0,al1,al2,al3, ql_b + aoff);
                #pragma unroll
                for (int np = 0; np < 4; ++np) {
                    const int brow = (2*np + ((lane >> 4) & 1)) * 8 + (lane & 7);
                    const int bch  = (k0 >> 3) + ((lane >> 3) & 1);
                    const uint32_t boff = swzb(brow, bch);
                    uint32_t bh0,bh1,bh2,bh3, bl0,bl1,bl2,bl3;
                    ldsm_x4(bh0,bh1,bh2,bh3, kh_b + boff);
                    ldsm_x4(bl0,bl1,bl2,bl3, kl_b + boff);
                    mma_bf16(cfr[2*np],   ah0,ah1,ah2,ah3, bh0,bh1);
                    mma_bf16(cfr[2*np+1], ah0,ah1,ah2,ah3, bh2,bh3);
                    mma_bf16(cfr[2*np],   ah0,ah1,ah2,ah3, bl0,bl1);
                    mma_bf16(cfr[2*np+1], ah0,ah1,ah2,ah3, bl2,bl3);
                    mma_bf16(cfr[2*np],   al0,al1,al2,al3, bh0,bh1);
                    mma_bf16(cfr[2*np+1], al0,al1,al2,al3, bh2,bh3);
                }
            }
        }

        // scale tile for this kt must be resident
        CPWAIT(1);
        __syncthreads();

        // ---- elementwise scale + online softmax ----
        const int r0 = wr + g, r1 = r0 + 8;
        float mx0 = -1e30f, mx1 = -1e30f;
        #pragma unroll
        for (int n = 0; n < 8; ++n) {
            float2 s0 = *(float2*)&sc[r0 * SC_STRIDE + n * 8 + qr * 2];
            float2 s1 = *(float2*)&sc[r1 * SC_STRIDE + n * 8 + qr * 2];
            cfr[n][0] *= s0.x; cfr[n][1] *= s0.y;
            cfr[n][2] *= s1.x; cfr[n][3] *= s1.y;
            mx0 = fmaxf(mx0, fmaxf(cfr[n][0], cfr[n][1]));
            mx1 = fmaxf(mx1, fmaxf(cfr[n][2], cfr[n][3]));
        }
        mx0 = fmaxf(mx0, __shfl_xor_sync(0xffffffffu, mx0, 1));
        mx0 = fmaxf(mx0, __shfl_xor_sync(0xffffffffu, mx0, 2));
        mx1 = fmaxf(mx1, __shfl_xor_sync(0xffffffffu, mx1, 1));
        mx1 = fmaxf(mx1, __shfl_xor_sync(0xffffffffu, mx1, 2));

        const float mn0 = fmaxf(m0, mx0), mn1 = fmaxf(m1, mx1);
        const float al0 = exp2f((m0 - mn0) * LOG2E);
        const float al1 = exp2f((m1 - mn1) * LOG2E);
        m0 = mn0; m1 = mn1;

        float rs0 = 0.f, rs1 = 0.f;
        #pragma unroll
        for (int n = 0; n < 8; ++n) {
            cfr[n][0] = exp2f((cfr[n][0] - m0) * LOG2E);
            cfr[n][1] = exp2f((cfr[n][1] - m0) * LOG2E);
            cfr[n][2] = exp2f((cfr[n][2] - m1) * LOG2E);
            cfr[n][3] = exp2f((cfr[n][3] - m1) * LOG2E);
            rs0 += cfr[n][0] + cfr[n][1];
            rs1 += cfr[n][2] + cfr[n][3];
        }
        rs0 += __shfl_xor_sync(0xffffffffu, rs0, 1);
        rs0 += __shfl_xor_sync(0xffffffffu, rs0, 2);
        rs1 += __shfl_xor_sync(0xffffffffu, rs1, 1);
        rs1 += __shfl_xor_sync(0xffffffffu, rs1, 2);
        l0 = l0 * al0 + rs0;
        l1 = l1 * al1 + rs1;

        #pragma unroll
        for (int n = 0; n < 16; ++n) {
            o[n][0] *= al0; o[n][1] *= al0;
            o[n][2] *= al1; o[n][3] *= al1;
        }

        // all sc reads done -> safe to refill sc for kt+1 (deadline: next softmax)
        __syncthreads();
        if (kt + 1 < NKT)
            issue_sc_tile(smem_b + SM_SC, SF + sf_base + (size_t)(kt + 1) * BK, tid);
        CPCOMMIT();

        // ---- O += P V, bf16x3 split, x4 transposed V loads ----
        {
            const uint32_t vh_b = stage + STG_VHI, vl_b = stage + STG_VLO;
            #pragma unroll
            for (int j = 0; j < 4; ++j) {
                float ph[8] = { cfr[2*j][0], cfr[2*j][1], cfr[2*j][2], cfr[2*j][3],
                                cfr[2*j+1][0], cfr[2*j+1][1], cfr[2*j+1][2], cfr[2*j+1][3] };
                float pl[8];
                #pragma unroll
                for (int t = 0; t < 8; ++t)
                    pl[t] = ph[t] - __bfloat162float(__float2bfloat16(ph[t]));
                uint32_t ah[4] = { packbf(ph[0], ph[1]), packbf(ph[2], ph[3]),
                                   packbf(ph[4], ph[5]), packbf(ph[6], ph[7]) };
                uint32_t al_[4] = { packbf(pl[0], pl[1]), packbf(pl[2], pl[3]),
                                    packbf(pl[4], pl[5]), packbf(pl[6], pl[7]) };
                const int k0 = j * 16;
                const int vrow = k0 + ((lane >> 3) & 1) * 8 + (lane & 7);
                #pragma unroll
                for (int np = 0; np < 8; ++np) {
                    const int vch = 2 * np + (lane >> 4);
                    const uint32_t voff = swzb(vrow, vch);
                    uint32_t bh0,bh1,bh2,bh3, bl0,bl1,bl2,bl3;
                    ldsm_x4t(bh0,bh1,bh2,bh3, vh_b + voff);
                    ldsm_x4t(bl0,bl1,bl2,bl3, vl_b + voff);
                    mma_bf16(o[2*np],   ah[0],ah[1],ah[2],ah[3], bh0,bh1);
                    mma_bf16(o[2*np+1], ah[0],ah[1],ah[2],ah[3], bh2,bh3);
                    mma_bf16(o[2*np],   ah[0],ah[1],ah[2],ah[3], bl0,bl1);
                    mma_bf16(o[2*np+1], ah[0],ah[1],ah[2],ah[3], bl2,bl3);
                    mma_bf16(o[2*np],   al_[0],al_[1],al_[2],al_[3], bh0,bh1);
                    mma_bf16(o[2*np+1], al_[0],al_[1],al_[2],al_[3], bh2,bh3);
                }
            }
        }

        // next K/V tile resident before flipping buffers
        CPWAIT(1);
        __syncthreads();
    }

    // ---- epilogue ----
    const float inv0 = 1.f / l0;
    const float inv1 = 1.f / l1;
    const size_t ob = ((size_t)b * LQ + (size_t)qb * BQ) * DD;
    const int r0 = wr + g, r1 = r0 + 8;
    #pragma unroll
    for (int n = 0; n < 16; ++n) {
        const int col = n * 8 + qr * 2;
        float2 t0; t0.x = o[n][0] * inv0; t0.y = o[n][1] * inv0;
        *(float2*)(O + ob + (size_t)r0 * DD + col) = t0;
        float2 t1; t1.x = o[n][2] * inv1; t1.y = o[n][3] * inv1;
        *(float2*)(O + ob + (size_t)r1 * DD + col) = t1;
    }
}

extern "C" void kernel_launch(void* const* d_in, const int* in_sizes, int n_in,
                              void* d_out, int out_size) {
    (void)in_sizes; (void)n_in; (void)out_size;
    const float* q  = (const float*)d_in[0];
    const float* k  = (const float*)d_in[1];
    const float* v  = (const float*)d_in[2];
    const float* sf = (const float*)d_in[3];
    float* out = (float*)d_out;

    split_kv_prepass<<<2048, 256>>>((const float4*)k, (const float4*)v);

    cudaFuncSetAttribute(Model_48876727828871_kernel,
                         cudaFuncAttributeMaxDynamicSharedMemorySize, SMEM_BYTES);
    dim3 grid(LQ / BQ, NB);
    Model_48876727828871_kernel<<<grid, THREADS, SMEM_BYTES>>>(q, sf, out);
}

// round 12
// speedup vs baseline: 2.0661x; 1.0956x over previous
#include <cuda_runtime.h>
#include <cuda_fp16.h>
#include <cstdint>

// Problem constants
#define NB   8
#define LQ   2048
#define LK   2048
#define DD   128
#define BQ   128
#define BK   64
#define THREADS 256            // 8 warps, each owns 16 Q rows
#define NKT  (LK / BK)
#define LOG2E 1.4426950408889634f

// SMEM map (bytes): 256B swizzled rows
#define SM_QHI   0             // 128x128 fp16 = 32768
#define SM_QLO   32768
#define SM_STG   65536         // 2 stages x {khi,klo,v}, 64x128 fp16 each
#define STG_KLO  16384
#define STG_V    32768
#define STG_SZ   49152
#define SMEM_BYTES (65536 + 2*STG_SZ)   // 163840

// Prepass scratch: K split fp16 hi/lo + V fp16 (24 MB)
__device__ __half g_khi[(size_t)NB * LK * DD];
__device__ __half g_klo[(size_t)NB * LK * DD];
__device__ __half g_v  [(size_t)NB * LK * DD];

__device__ __forceinline__ uint32_t smem_u32(const void* p) {
    return (uint32_t)__cvta_generic_to_shared(p);
}
// XOR swizzle: 256B rows, 16B chunks; low-3 chunk bits XOR row&7.
__device__ __forceinline__ uint32_t swzb(int row, int ch) {
    return (uint32_t)(row * 256 + ((((ch ^ row) & 7) | (ch & 8)) << 4));
}
__device__ __forceinline__ void ldsm_x4(uint32_t& r0, uint32_t& r1, uint32_t& r2, uint32_t& r3, uint32_t a) {
    asm volatile("ldmatrix.sync.aligned.m8n8.x4.shared.b16 {%0,%1,%2,%3}, [%4];\n"
        : "=r"(r0), "=r"(r1), "=r"(r2), "=r"(r3) : "r"(a));
}
__device__ __forceinline__ void ldsm_x4t(uint32_t& r0, uint32_t& r1, uint32_t& r2, uint32_t& r3, uint32_t a) {
    asm volatile("ldmatrix.sync.aligned.m8n8.x4.trans.shared.b16 {%0,%1,%2,%3}, [%4];\n"
        : "=r"(r0), "=r"(r1), "=r"(r2), "=r"(r3) : "r"(a));
}
__device__ __forceinline__ void mma_f16(float* c,
    uint32_t a0, uint32_t a1, uint32_t a2, uint32_t a3, uint32_t b0, uint32_t b1) {
    asm volatile(
      "mma.sync.aligned.m16n8k16.row.col.f32.f16.f16.f32 "
      "{%0,%1,%2,%3}, {%4,%5,%6,%7}, {%8,%9}, {%0,%1,%2,%3};\n"
      : "+f"(c[0]), "+f"(c[1]), "+f"(c[2]), "+f"(c[3])
      : "r"(a0), "r"(a1), "r"(a2), "r"(a3), "r"(b0), "r"(b1));
}
// pack two fp32 -> f16x2 (lo half = x, hi half = y), round-to-nearest
__device__ __forceinline__ uint32_t packh(float x, float y) {
    uint32_t r;
    asm("cvt.rn.f16x2.f32 %0, %1, %2;\n" : "=r"(r) : "f"(y), "f"(x));
    return r;
}
__device__ __forceinline__ float hif(float x) {
    return __half2float(__float2half_rn(x));
}
__device__ __forceinline__ void split_store4h(float4 x, __half* hi, __half* lo) {
    *(uint32_t*)(hi)     = packh(x.x, x.y);
    *(uint32_t*)(hi + 2) = packh(x.z, x.w);
    *(uint32_t*)(lo)     = packh(x.x - hif(x.x), x.y - hif(x.y));
    *(uint32_t*)(lo + 2) = packh(x.z - hif(x.z), x.w - hif(x.w));
}

#define CP16(dst, src) asm volatile("cp.async.cg.shared.global [%0], [%1], 16;\n" :: "r"(dst), "l"(src))
#define CPCOMMIT()     asm volatile("cp.async.commit_group;\n" ::: "memory")
#define CPWAIT(n)      asm volatile("cp.async.wait_group %0;\n" :: "n"(n) : "memory")

// ---- prepass: K -> fp16 hi/lo, V -> fp16 ----
__global__ void split_k_prepass(const float4* __restrict__ K) {
    const int n4 = NB * LK * DD / 4;
    for (int i = blockIdx.x * blockDim.x + threadIdx.x; i < n4; i += gridDim.x * blockDim.x) {
        float4 x = K[i];
        split_store4h(x, g_khi + (size_t)i * 4, g_klo + (size_t)i * 4);
    }
}
__global__ void conv_v_prepass(const float4* __restrict__ V) {
    const int n4 = NB * LK * DD / 4;
    for (int i = blockIdx.x * blockDim.x + threadIdx.x; i < n4; i += gridDim.x * blockDim.x) {
        float4 x = V[i];
        uint2 p; p.x = packh(x.x, x.y); p.y = packh(x.z, x.w);
        *(uint2*)(g_v + (size_t)i * 4) = p;
    }
}

// cp.async one K/V tile (khi, klo, v) into a stage buffer
__device__ __forceinline__ void issue_kv(uint32_t stg,
    const __half* __restrict__ khi, const __half* __restrict__ klo,
    const __half* __restrict__ v, int tid) {
    #pragma unroll
    for (int t = 0; t < 4; ++t) {
        int i = tid + t * THREADS;          // 1024 chunks: 64 rows x 16
        int r = i >> 4, ch = i & 15;
        uint32_t d = swzb(r, ch);
        const size_t off = (size_t)r * DD + ch * 8;
        CP16(stg + d,           khi + off);
        CP16(stg + STG_KLO + d, klo + off);
        CP16(stg + STG_V + d,   v   + off);
    }
}

__global__ void __launch_bounds__(THREADS, 1)
Model_48876727828871_kernel(const float* __restrict__ Q, const float* __restrict__ SF,
                            float* __restrict__ O) {
    extern __shared__ char smem[];
    const uint32_t smb = smem_u32(smem);

    const int tid  = threadIdx.x;
    const int lane = tid & 31;
    const int w    = tid >> 5;
    const int qb   = blockIdx.x;
    const int b    = blockIdx.y;

    const size_t q_base  = ((size_t)b * LQ + (size_t)qb * BQ) * DD;
    const size_t kv_base = (size_t)b * LK * DD;
    const size_t sf_base = ((size_t)b * LQ + (size_t)qb * BQ) * LK;
    const __half* khi_b = g_khi + kv_base;
    const __half* klo_b = g_klo + kv_base;
    const __half* v_b   = g_v   + kv_base;

    // prologue: tiles 0 and 1 in flight
    issue_kv(smb + SM_STG,          khi_b,           klo_b,           v_b,           tid);
    CPCOMMIT();
    issue_kv(smb + SM_STG + STG_SZ, khi_b + BK * DD, klo_b + BK * DD, v_b + BK * DD, tid);
    CPCOMMIT();

    // load + split Q tile
    #pragma unroll 4
    for (int i = tid; i < BQ * (DD / 4); i += THREADS) {
        int r  = i >> 5;
        int c4 = (i & 31) << 2;
        float4 x = *(const float4*)(Q + q_base + (size_t)r * DD + c4);
        uint32_t off = swzb(r, c4 >> 3) + (c4 & 4) * 2;
        split_store4h(x, (__half*)(smem + SM_QHI + off), (__half*)(smem + SM_QLO + off));
    }
    CPWAIT(1);                 // tile 0 resident
    __syncthreads();

    // accumulators
    float o[16][4];
    #pragma unroll
    for (int n = 0; n < 16; ++n) { o[n][0]=0.f; o[n][1]=0.f; o[n][2]=0.f; o[n][3]=0.f; }
    float m0 = -1e30f, m1 = -1e30f, l0 = 0.f, l1 = 0.f;

    const int wr = w * 16;
    const int g  = lane >> 2;
    const int qr = lane & 3;
    const int r0 = wr + g, r1 = r0 + 8;
    const uint32_t qh_b = smb + SM_QHI;
    const uint32_t ql_b = smb + SM_QLO;
    const float* sfp = SF + sf_base + (size_t)r0 * LK + qr * 2;

    for (int kt = 0; kt < NKT; ++kt) {
        const uint32_t stg = smb + SM_STG + (kt & 1) * STG_SZ;

        // SF prefetch straight to registers (streaming; consumed after QK)
        float2 s0[8], s1[8];
        #pragma unroll
        for (int n = 0; n < 8; ++n) {
            s0[n] = __ldcs((const float2*)(sfp + kt * BK + n * 8));
            s1[n] = __ldcs((const float2*)(sfp + kt * BK + n * 8 + 8 * LK));
        }

        // ---- S = Q K^T, fp16x3 split ----
        float cfr[8][4];
        #pragma unroll
        for (int n = 0; n < 8; ++n) { cfr[n][0]=0.f; cfr[n][1]=0.f; cfr[n][2]=0.f; cfr[n][3]=0.f; }
        {
            const uint32_t kh_b = stg, kl_b = stg + STG_KLO;
            #pragma unroll
            for (int kk = 0; kk < 8; ++kk) {
                const int arow = wr + (lane & 15);
                const int ach  = kk * 2 + (lane >> 4);
                const uint32_t aoff = swzb(arow, ach);
                uint32_t ah0,ah1,ah2,ah3, al0,al1,al2,al3;
                ldsm_x4(ah0,ah1,ah2,ah3, qh_b + aoff);
                ldsm_x4(al0,al1,al2,al3, ql_b + aoff);
                #pragma unroll
                for (int np = 0; np < 4; ++np) {
                    const int brow = (2*np + ((lane >> 4) & 1)) * 8 + (lane & 7);
                    const int bch  = kk * 2 + ((lane >> 3) & 1);
                    const uint32_t boff = swzb(brow, bch);
                    uint32_t bh0,bh1,bh2,bh3, bl0,bl1,bl2,bl3;
                    ldsm_x4(bh0,bh1,bh2,bh3, kh_b + boff);
                    ldsm_x4(bl0,bl1,bl2,bl3, kl_b + boff);
                    mma_f16(cfr[2*np],   ah0,ah1,ah2,ah3, bh0,bh1);
                    mma_f16(cfr[2*np+1], ah0,ah1,ah2,ah3, bh2,bh3);
                    mma_f16(cfr[2*np],   ah0,ah1,ah2,ah3, bl0,bl1);
                    mma_f16(cfr[2*np+1], ah0,ah1,ah2,ah3, bl2,bl3);
                    mma_f16(cfr[2*np],   al0,al1,al2,al3, bh0,bh1);
                    mma_f16(cfr[2*np+1], al0,al1,al2,al3, bh2,bh3);
                }
            }
        }

        // ---- scale + row max (warp-local) ----
        float mx0 = -1e30f, mx1 = -1e30f;
        #pragma unroll
        for (int n = 0; n < 8; ++n) {
            cfr[n][0] *= s0[n].x; cfr[n][1] *= s0[n].y;
            cfr[n][2] *= s1[n].x; cfr[n][3] *= s1[n].y;
            mx0 = fmaxf(mx0, fmaxf(cfr[n][0], cfr[n][1]));
            mx1 = fmaxf(mx1, fmaxf(cfr[n][2], cfr[n][3]));
        }
        mx0 = fmaxf(mx0, __shfl_xor_sync(0xffffffffu, mx0, 1));
        mx0 = fmaxf(mx0, __shfl_xor_sync(0xffffffffu, mx0, 2));
        mx1 = fmaxf(mx1, __shfl_xor_sync(0xffffffffu, mx1, 1));
        mx1 = fmaxf(mx1, __shfl_xor_sync(0xffffffffu, mx1, 2));

        const float mn0 = fmaxf(m0, mx0), mn1 = fmaxf(m1, mx1);
        const float al0 = exp2f((m0 - mn0) * LOG2E);
        const float al1 = exp2f((m1 - mn1) * LOG2E);
        m0 = mn0; m1 = mn1;

        // rescale O before PV accumulation
        #pragma unroll
        for (int n = 0; n < 16; ++n) {
            o[n][0] *= al0; o[n][1] *= al0;
            o[n][2] *= al1; o[n][3] *= al1;
        }

        // ---- interleaved per-j: exp + pack + PV MMAs (P hi/lo, V single fp16) ----
        float rs0 = 0.f, rs1 = 0.f;
        const uint32_t v_bse = stg + STG_V;
        #pragma unroll
        for (int j = 0; j < 4; ++j) {
            #pragma unroll
            for (int t = 2*j; t < 2*j+2; ++t) {
                cfr[t][0] = exp2f((cfr[t][0] - m0) * LOG2E);
                cfr[t][1] = exp2f((cfr[t][1] - m0) * LOG2E);
                cfr[t][2] = exp2f((cfr[t][2] - m1) * LOG2E);
                cfr[t][3] = exp2f((cfr[t][3] - m1) * LOG2E);
                rs0 += cfr[t][0] + cfr[t][1];
                rs1 += cfr[t][2] + cfr[t][3];
            }
            uint32_t ah[4], al_[4];
            #pragma unroll
            for (int c = 0; c < 4; ++c) {
                const float pa = cfr[2*j + (c >> 1)][(c & 1) * 2];
                const float pb = cfr[2*j + (c >> 1)][(c & 1) * 2 + 1];
                ah[c]  = packh(pa, pb);
                al_[c] = packh(pa - hif(pa), pb - hif(pb));
            }
            const int vrow = j * 16 + ((lane >> 3) & 1) * 8 + (lane & 7);
            #pragma unroll
            for (int np = 0; np < 8; ++np) {
                const int vch = 2 * np + (lane >> 4);
                uint32_t bh0,bh1,bh2,bh3;
                ldsm_x4t(bh0,bh1,bh2,bh3, v_bse + swzb(vrow, vch));
                mma_f16(o[2*np],   ah[0],ah[1],ah[2],ah[3],     bh0,bh1);
                mma_f16(o[2*np+1], ah[0],ah[1],ah[2],ah[3],     bh2,bh3);
                mma_f16(o[2*np],   al_[0],al_[1],al_[2],al_[3], bh0,bh1);
                mma_f16(o[2*np+1], al_[0],al_[1],al_[2],al_[3], bh2,bh3);
            }
        }
        rs0 += __shfl_xor_sync(0xffffffffu, rs0, 1);
        rs0 += __shfl_xor_sync(0xffffffffu, rs0, 2);
        rs1 += __shfl_xor_sync(0xffffffffu, rs1, 1);
        rs1 += __shfl_xor_sync(0xffffffffu, rs1, 2);
        l0 = l0 * al0 + rs0;
        l1 = l1 * al1 + rs1;

        // single barrier per tile: next tile resident + this stage fully read
        CPWAIT(0);
        __syncthreads();
        if (kt + 2 < NKT) {
            const size_t off = (size_t)(kt + 2) * BK * DD;
            issue_kv(stg, khi_b + off, klo_b + off, v_b + off, tid);
            CPCOMMIT();
        }
    }

    // ---- epilogue ----
    const float inv0 = 1.f / l0;
    const float inv1 = 1.f / l1;
    const size_t ob = q_base;
    #pragma unroll
    for (int n = 0; n < 16; ++n) {
        const int col = n * 8 + qr * 2;
        float2 t0; t0.x = o[n][0] * inv0; t0.y = o[n][1] * inv0;
        *(float2*)(O + ob + (size_t)r0 * DD + col) = t0;
        float2 t1; t1.x = o[n][2] * inv1; t1.y = o[n][3] * inv1;
        *(float2*)(O + ob + (size_t)r1 * DD + col) = t1;
    }
}

extern "C" void kernel_launch(void* const* d_in, const int* in_sizes, int n_in,
                              void* d_out, int out_size) {
    (void)in_sizes; (void)n_in; (void)out_size;
    const float* q  = (const float*)d_in[0];
    const float* k  = (const float*)d_in[1];
    const float* v  = (const float*)d_in[2];
    const float* sf = (const float*)d_in[3];
    float* out = (float*)d_out;

    split_k_prepass<<<1024, 256>>>((const float4*)k);
    conv_v_prepass<<<1024, 256>>>((const float4*)v);

    cudaFuncSetAttribute(Model_48876727828871_kernel,
                         cudaFuncAttributeMaxDynamicSharedMemorySize, SMEM_BYTES);
    dim3 grid(LQ / BQ, NB);
    Model_48876727828871_kernel<<<grid, THREADS, SMEM_BYTES>>>(q, sf, out);
}

// round 14
// speedup vs baseline: 2.0927x; 1.0129x over previous
#include <cuda_runtime.h>
#include <cuda_fp16.h>
#include <cstdint>

// Problem constants
#define NB   8
#define LQ   2048
#define LK   2048
#define DD   128
#define BQ   128
#define BK   64
#define THREADS 256            // 8 warps, each owns 16 Q rows
#define NKT  (LK / BK)
#define LOG2E 1.4426950408889634f

// SMEM map (bytes): 256B swizzled rows
#define SM_QHI   0             // 128x128 fp16 = 32768
#define SM_QLO   32768
#define SM_STG   65536         // 2 stages x {khi,klo,v}, 64x128 fp16 each
#define STG_KLO  16384
#define STG_V    32768
#define STG_SZ   49152
#define SMEM_BYTES (65536 + 2*STG_SZ)   // 163840

// Prepass scratch: K split fp16 hi/lo + V fp16 (24 MB)
__device__ __half g_khi[(size_t)NB * LK * DD];
__device__ __half g_klo[(size_t)NB * LK * DD];
__device__ __half g_v  [(size_t)NB * LK * DD];

__device__ __forceinline__ uint32_t smem_u32(const void* p) {
    return (uint32_t)__cvta_generic_to_shared(p);
}
// XOR swizzle: 256B rows, 16B chunks; low-3 chunk bits XOR row&7.
__device__ __forceinline__ uint32_t swzb(int row, int ch) {
    return (uint32_t)(row * 256 + ((((ch ^ row) & 7) | (ch & 8)) << 4));
}
__device__ __forceinline__ void ldsm_x4(uint32_t& r0, uint32_t& r1, uint32_t& r2, uint32_t& r3, uint32_t a) {
    asm volatile("ldmatrix.sync.aligned.m8n8.x4.shared.b16 {%0,%1,%2,%3}, [%4];\n"
        : "=r"(r0), "=r"(r1), "=r"(r2), "=r"(r3) : "r"(a));
}
__device__ __forceinline__ void ldsm_x4t(uint32_t& r0, uint32_t& r1, uint32_t& r2, uint32_t& r3, uint32_t a) {
    asm volatile("ldmatrix.sync.aligned.m8n8.x4.trans.shared.b16 {%0,%1,%2,%3}, [%4];\n"
        : "=r"(r0), "=r"(r1), "=r"(r2), "=r"(r3) : "r"(a));
}
__device__ __forceinline__ void mma_f16(float* c,
    uint32_t a0, uint32_t a1, uint32_t a2, uint32_t a3, uint32_t b0, uint32_t b1) {
    asm volatile(
      "mma.sync.aligned.m16n8k16.row.col.f32.f16.f16.f32 "
      "{%0,%1,%2,%3}, {%4,%5,%6,%7}, {%8,%9}, {%0,%1,%2,%3};\n"
      : "+f"(c[0]), "+f"(c[1]), "+f"(c[2]), "+f"(c[3])
      : "r"(a0), "r"(a1), "r"(a2), "r"(a3), "r"(b0), "r"(b1));
}
// pack two fp32 -> f16x2 (lo half = x, hi half = y), round-to-nearest
__device__ __forceinline__ uint32_t packh(float x, float y) {
    uint32_t r;
    asm("cvt.rn.f16x2.f32 %0, %1, %2;\n" : "=r"(r) : "f"(y), "f"(x));
    return r;
}
__device__ __forceinline__ float hif(float x) {
    return __half2float(__float2half_rn(x));
}
__device__ __forceinline__ void split_store4h(float4 x, __half* hi, __half* lo) {
    *(uint32_t*)(hi)     = packh(x.x, x.y);
    *(uint32_t*)(hi + 2) = packh(x.z, x.w);
    *(uint32_t*)(lo)     = packh(x.x - hif(x.x), x.y - hif(x.y));
    *(uint32_t*)(lo + 2) = packh(x.z - hif(x.z), x.w - hif(x.w));
}

#define CP16(dst, src) asm volatile("cp.async.cg.shared.global [%0], [%1], 16;\n" :: "r"(dst), "l"(src))
#define CPCOMMIT()     asm volatile("cp.async.commit_group;\n" ::: "memory")
#define CPWAIT(n)      asm volatile("cp.async.wait_group %0;\n" :: "n"(n) : "memory")

// ---- fused prepass: K -> fp16 hi/lo, V -> fp16 ----
__global__ void prepass_kv(const float4* __restrict__ K, const float4* __restrict__ V) {
    const int n4 = NB * LK * DD / 4;
    for (int i = blockIdx.x * blockDim.x + threadIdx.x; i < n4; i += gridDim.x * blockDim.x) {
        float4 xk = K[i];
        split_store4h(xk, g_khi + (size_t)i * 4, g_klo + (size_t)i * 4);
        float4 xv = V[i];
        uint2 p; p.x = packh(xv.x, xv.y); p.y = packh(xv.z, xv.w);
        *(uint2*)(g_v + (size_t)i * 4) = p;
    }
}

// cp.async one K/V tile (khi, klo, v) into a stage buffer
__device__ __forceinline__ void issue_kv(uint32_t stg,
    const __half* __restrict__ khi, const __half* __restrict__ klo,
    const __half* __restrict__ v, int tid) {
    #pragma unroll
    for (int t = 0; t < 4; ++t) {
        int i = tid + t * THREADS;          // 1024 chunks: 64 rows x 16
        int r = i >> 4, ch = i & 15;
        uint32_t d = swzb(r, ch);
        const size_t off = (size_t)r * DD + ch * 8;
        CP16(stg + d,           khi + off);
        CP16(stg + STG_KLO + d, klo + off);
        CP16(stg + STG_V + d,   v   + off);
    }
}

__global__ void __launch_bounds__(THREADS, 1)
Model_48876727828871_kernel(const float* __restrict__ Q, const float* __restrict__ SF,
                            float* __restrict__ O) {
    extern __shared__ char smem[];
    const uint32_t smb = smem_u32(smem);

    const int tid  = threadIdx.x;
    const int lane = tid & 31;
    const int w    = tid >> 5;
    const int qb   = blockIdx.x;
    const int b    = blockIdx.y;

    const size_t q_base  = ((size_t)b * LQ + (size_t)qb * BQ) * DD;
    const size_t kv_base = (size_t)b * LK * DD;
    const size_t sf_base = ((size_t)b * LQ + (size_t)qb * BQ) * LK;
    const __half* khi_b = g_khi + kv_base;
    const __half* klo_b = g_klo + kv_base;
    const __half* v_b   = g_v   + kv_base;

    // prologue: tiles 0 and 1 in flight
    issue_kv(smb + SM_STG,          khi_b,           klo_b,           v_b,           tid);
    CPCOMMIT();
    issue_kv(smb + SM_STG + STG_SZ, khi_b + BK * DD, klo_b + BK * DD, v_b + BK * DD, tid);
    CPCOMMIT();

    // load + split Q tile
    #pragma unroll 4
    for (int i = tid; i < BQ * (DD / 4); i += THREADS) {
        int r  = i >> 5;
        int c4 = (i & 31) << 2;
        float4 x = *(const float4*)(Q + q_base + (size_t)r * DD + c4);
        uint32_t off = swzb(r, c4 >> 3) + (c4 & 4) * 2;
        split_store4h(x, (__half*)(smem + SM_QHI + off), (__half*)(smem + SM_QLO + off));
    }
    CPWAIT(1);                 // tile 0 resident
    __syncthreads();

    // accumulators
    float o[16][4];
    #pragma unroll
    for (int n = 0; n < 16; ++n) { o[n][0]=0.f; o[n][1]=0.f; o[n][2]=0.f; o[n][3]=0.f; }
    float m0 = -1e30f, m1 = -1e30f, l0 = 0.f, l1 = 0.f;

    const int wr = w * 16;
    const int g  = lane >> 2;
    const int qr = lane & 3;
    const int r0 = wr + g, r1 = r0 + 8;
    const uint32_t qh_b = smb + SM_QHI;
    const uint32_t ql_b = smb + SM_QLO;
    const float* sfp = SF + sf_base + (size_t)r0 * LK + qr * 2;

    for (int kt = 0; kt < NKT; ++kt) {
        const uint32_t stg = smb + SM_STG + (kt & 1) * STG_SZ;

        // SF prefetch straight to registers (streaming; consumed after QK)
        float2 s0[8], s1[8];
        #pragma unroll
        for (int n = 0; n < 8; ++n) {
            s0[n] = __ldcs((const float2*)(sfp + kt * BK + n * 8));
            s1[n] = __ldcs((const float2*)(sfp + kt * BK + n * 8 + 8 * LK));
        }

        // ---- S = Q K^T, fp16x3 split; term-pass ordering for MMA ILP ----
        float cfr[8][4];
        #pragma unroll
        for (int n = 0; n < 8; ++n) { cfr[n][0]=0.f; cfr[n][1]=0.f; cfr[n][2]=0.f; cfr[n][3]=0.f; }
        {
            const uint32_t kh_b = stg, kl_b = stg + STG_KLO;
            const int arow  = wr + (lane & 15);
            const int brow_ = ((lane >> 4) & 1) * 8 + (lane & 7);
            #pragma unroll
            for (int kk = 0; kk < 8; ++kk) {
                const int ach = kk * 2 + (lane >> 4);
                const int bch = kk * 2 + ((lane >> 3) & 1);
                const uint32_t aoff = swzb(arow, ach);
                uint32_t ah0,ah1,ah2,ah3, al0,al1,al2,al3;
                ldsm_x4(ah0,ah1,ah2,ah3, qh_b + aoff);
                ldsm_x4(al0,al1,al2,al3, ql_b + aoff);
                // batch-load all B fragments for this kk (8x ldsm_x4 -> 32 regs)
                uint32_t bh[4][4], bl[4][4];
                #pragma unroll
                for (int np = 0; np < 4; ++np) {
                    const uint32_t boff = swzb(np * 16 + brow_, bch);
                    ldsm_x4(bh[np][0], bh[np][1], bh[np][2], bh[np][3], kh_b + boff);
                    ldsm_x4(bl[np][0], bl[np][1], bl[np][2], bl[np][3], kl_b + boff);
                }
                // three term passes; same-accumulator distance = 8 MMAs
                #pragma unroll
                for (int np = 0; np < 4; ++np) {
                    mma_f16(cfr[2*np],   ah0,ah1,ah2,ah3, bh[np][0], bh[np][1]);
                    mma_f16(cfr[2*np+1], ah0,ah1,ah2,ah3, bh[np][2], bh[np][3]);
                }
                #pragma unroll
                for (int np = 0; np < 4; ++np) {
                    mma_f16(cfr[2*np],   ah0,ah1,ah2,ah3, bl[np][0], bl[np][1]);
                    mma_f16(cfr[2*np+1], ah0,ah1,ah2,ah3, bl[np][2], bl[np][3]);
                }
                #pragma unroll
                for (int np = 0; np < 4; ++np) {
                    mma_f16(cfr[2*np],   al0,al1,al2,al3, bh[np][0], bh[np][1]);
                    mma_f16(cfr[2*np+1], al0,al1,al2,al3, bh[np][2], bh[np][3]);
                }
            }
        }

        // ---- scale + row max (warp-local) ----
        float mx0 = -1e30f, mx1 = -1e30f;
        #pragma unroll
        for (int n = 0; n < 8; ++n) {
            cfr[n][0] *= s0[n].x; cfr[n][1] *= s0[n].y;
            cfr[n][2] *= s1[n].x; cfr[n][3] *= s1[n].y;
            mx0 = fmaxf(mx0, fmaxf(cfr[n][0], cfr[n][1]));
            mx1 = fmaxf(mx1, fmaxf(cfr[n][2], cfr[n][3]));
        }
        mx0 = fmaxf(mx0, __shfl_xor_sync(0xffffffffu, mx0, 1));
        mx0 = fmaxf(mx0, __shfl_xor_sync(0xffffffffu, mx0, 2));
        mx1 = fmaxf(mx1, __shfl_xor_sync(0xffffffffu, mx1, 1));
        mx1 = fmaxf(mx1, __shfl_xor_sync(0xffffffffu, mx1, 2));

        const float mn0 = fmaxf(m0, mx0), mn1 = fmaxf(m1, mx1);
        const float al0 = exp2f((m0 - mn0) * LOG2E);
        const float al1 = exp2f((m1 - mn1) * LOG2E);
        m0 = mn0; m1 = mn1;

        // rescale O before PV accumulation
        #pragma unroll
        for (int n = 0; n < 16; ++n) {
            o[n][0] *= al0; o[n][1] *= al0;
            o[n][2] *= al1; o[n][3] *= al1;
        }

        // ---- per-j: exp + pack, then hi-pass / lo-pass PV MMAs ----
        float rs0 = 0.f, rs1 = 0.f;
        const uint32_t v_bse = stg + STG_V;
        #pragma unroll
        for (int j = 0; j < 4; ++j) {
            #pragma unroll
            for (int t = 2*j; t < 2*j+2; ++t) {
                cfr[t][0] = exp2f((cfr[t][0] - m0) * LOG2E);
                cfr[t][1] = exp2f((cfr[t][1] - m0) * LOG2E);
                cfr[t][2] = exp2f((cfr[t][2] - m1) * LOG2E);
                cfr[t][3] = exp2f((cfr[t][3] - m1) * LOG2E);
                rs0 += cfr[t][0] + cfr[t][1];
                rs1 += cfr[t][2] + cfr[t][3];
            }
            uint32_t ah[4], al_[4];
            #pragma unroll
            for (int c = 0; c < 4; ++c) {
                const float pa = cfr[2*j + (c >> 1)][(c & 1) * 2];
                const float pb = cfr[2*j + (c >> 1)][(c & 1) * 2 + 1];
                ah[c]  = packh(pa, pb);
                al_[c] = packh(pa - hif(pa), pb - hif(pb));
            }
            // batch-load all V fragments for this j (8x ldsm_x4t -> 32 regs)
            const int vrow = j * 16 + ((lane >> 3) & 1) * 8 + (lane & 7);
            uint32_t vh[8][4];
            #pragma unroll
            for (int np = 0; np < 8; ++np) {
                const int vch = 2 * np + (lane >> 4);
                ldsm_x4t(vh[np][0], vh[np][1], vh[np][2], vh[np][3], v_bse + swzb(vrow, vch));
            }
            // hi pass then lo pass; same-accumulator distance = 16 MMAs
            #pragma unroll
            for (int np = 0; np < 8; ++np) {
                mma_f16(o[2*np],   ah[0],ah[1],ah[2],ah[3], vh[np][0], vh[np][1]);
                mma_f16(o[2*np+1], ah[0],ah[1],ah[2],ah[3], vh[np][2], vh[np][3]);
            }
            #pragma unroll
            for (int np = 0; np < 8; ++np) {
                mma_f16(o[2*np],   al_[0],al_[1],al_[2],al_[3], vh[np][0], vh[np][1]);
                mma_f16(o[2*np+1], al_[0],al_[1],al_[2],al_[3], vh[np][2], vh[np][3]);
            }
        }
        rs0 += __shfl_xor_sync(0xffffffffu, rs0, 1);
        rs0 += __shfl_xor_sync(0xffffffffu, rs0, 2);
        rs1 += __shfl_xor_sync(0xffffffffu, rs1, 1);
        rs1 += __shfl_xor_sync(0xffffffffu, rs1, 2);
        l0 = l0 * al0 + rs0;
        l1 = l1 * al1 + rs1;

        // single barrier per tile: next tile resident + this stage fully read
        CPWAIT(0);
        __syncthreads();
        if (kt + 2 < NKT) {
            const size_t off = (size_t)(kt + 2) * BK * DD;
            issue_kv(stg, khi_b + off, klo_b + off, v_b + off, tid);
            CPCOMMIT();
        }
    }

    // ---- epilogue ----
    const float inv0 = 1.f / l0;
    const float inv1 = 1.f / l1;
    const size_t ob = q_base;
    #pragma unroll
    for (int n = 0; n < 16; ++n) {
        const int col = n * 8 + qr * 2;
        float2 t0; t0.x = o[n][0] * inv0; t0.y = o[n][1] * inv0;
        *(float2*)(O + ob + (size_t)r0 * DD + col) = t0;
        float2 t1; t1.x = o[n][2] * inv1; t1.y = o[n][3] * inv1;
        *(float2*)(O + ob + (size_t)r1 * DD + col) = t1;
    }
}

extern "C" void kernel_launch(void* const* d_in, const int* in_sizes, int n_in,
                              void* d_out, int out_size) {
    (void)in_sizes; (void)n_in; (void)out_size;
    const float* q  = (const float*)d_in[0];
    const float* k  = (const float*)d_in[1];
    const float* v  = (const float*)d_in[2];
    const float* sf = (const float*)d_in[3];
    float* out = (float*)d_out;

    prepass_kv<<<1024, 256>>>((const float4*)k, (const float4*)v);

    cudaFuncSetAttribute(Model_48876727828871_kernel,
                         cudaFuncAttributeMaxDynamicSharedMemorySize, SMEM_BYTES);
    dim3 grid(LQ / BQ, NB);
    Model_48876727828871_kernel<<<grid, THREADS, SMEM_BYTES>>>(q, sf, out);
}

// round 15
// speedup vs baseline: 2.2961x; 1.0972x over previous
#include <cuda_runtime.h>
#include <cuda_fp16.h>
#include <cstdint>

// Problem constants
#define NB   8
#define LQ   2048
#define LK   2048
#define DD   128
#define BQ   128
#define BK   64
#define THREADS 256            // 8 warps, each owns 16 Q rows
#define NKT  (LK / BK)
#define LOG2E 1.4426950408889634f

// SMEM map (bytes): 256B swizzled rows
#define SM_QHI   0             // 128x128 fp16 = 32768
#define SM_QLO   32768
#define SM_K     65536         // 2 K-buffers {khi,klo} 32KB each
#define KBUF_SZ  32768
#define SM_V     131072        // 3 V-buffers 16KB each
#define VBUF_SZ  16384
#define SMEM_BYTES 180224      // 64K Q + 64K K + 48K V

// Prepass scratch: K split fp16 hi/lo + V fp16 (24 MB)
__device__ __half g_khi[(size_t)NB * LK * DD];
__device__ __half g_klo[(size_t)NB * LK * DD];
__device__ __half g_v  [(size_t)NB * LK * DD];

__device__ __forceinline__ uint32_t smem_u32(const void* p) {
    return (uint32_t)__cvta_generic_to_shared(p);
}
// XOR swizzle: 256B rows, 16B chunks; low-3 chunk bits XOR row&7.
__device__ __forceinline__ uint32_t swzb(int row, int ch) {
    return (uint32_t)(row * 256 + ((((ch ^ row) & 7) | (ch & 8)) << 4));
}
__device__ __forceinline__ void ldsm_x4(uint32_t& r0, uint32_t& r1, uint32_t& r2, uint32_t& r3, uint32_t a) {
    asm volatile("ldmatrix.sync.aligned.m8n8.x4.shared.b16 {%0,%1,%2,%3}, [%4];\n"
        : "=r"(r0), "=r"(r1), "=r"(r2), "=r"(r3) : "r"(a));
}
__device__ __forceinline__ void ldsm_x4t(uint32_t& r0, uint32_t& r1, uint32_t& r2, uint32_t& r3, uint32_t a) {
    asm volatile("ldmatrix.sync.aligned.m8n8.x4.trans.shared.b16 {%0,%1,%2,%3}, [%4];\n"
        : "=r"(r0), "=r"(r1), "=r"(r2), "=r"(r3) : "r"(a));
}
__device__ __forceinline__ void mma_f16(float* c,
    uint32_t a0, uint32_t a1, uint32_t a2, uint32_t a3, uint32_t b0, uint32_t b1) {
    asm volatile(
      "mma.sync.aligned.m16n8k16.row.col.f32.f16.f16.f32 "
      "{%0,%1,%2,%3}, {%4,%5,%6,%7}, {%8,%9}, {%0,%1,%2,%3};\n"
      : "+f"(c[0]), "+f"(c[1]), "+f"(c[2]), "+f"(c[3])
      : "r"(a0), "r"(a1), "r"(a2), "r"(a3), "r"(b0), "r"(b1));
}
__device__ __forceinline__ uint32_t packh(float x, float y) {
    uint32_t r;
    asm("cvt.rn.f16x2.f32 %0, %1, %2;\n" : "=r"(r) : "f"(y), "f"(x));
    return r;
}
__device__ __forceinline__ float hif(float x) {
    return __half2float(__float2half_rn(x));
}
__device__ __forceinline__ void split_store4h(float4 x, __half* hi, __half* lo) {
    *(uint32_t*)(hi)     = packh(x.x, x.y);
    *(uint32_t*)(hi + 2) = packh(x.z, x.w);
    *(uint32_t*)(lo)     = packh(x.x - hif(x.x), x.y - hif(x.y));
    *(uint32_t*)(lo + 2) = packh(x.z - hif(x.z), x.w - hif(x.w));
}

#define CP16(dst, src) asm volatile("cp.async.cg.shared.global [%0], [%1], 16;\n" :: "r"(dst), "l"(src))
#define CPCOMMIT()     asm volatile("cp.async.commit_group;\n" ::: "memory")
#define CPWAIT(n)      asm volatile("cp.async.wait_group %0;\n" :: "n"(n) : "memory")

// ---- fused prepass: K -> fp16 hi/lo, V -> fp16 ----
__global__ void prepass_kv(const float4* __restrict__ K, const float4* __restrict__ V) {
    const int n4 = NB * LK * DD / 4;
    for (int i = blockIdx.x * blockDim.x + threadIdx.x; i < n4; i += gridDim.x * blockDim.x) {
        float4 xk = K[i];
        split_store4h(xk, g_khi + (size_t)i * 4, g_klo + (size_t)i * 4);
        float4 xv = V[i];
        uint2 p; p.x = packh(xv.x, xv.y); p.y = packh(xv.z, xv.w);
        *(uint2*)(g_v + (size_t)i * 4) = p;
    }
}

__device__ __forceinline__ void issue_k(uint32_t dst,
    const __half* __restrict__ khi, const __half* __restrict__ klo, int tid) {
    #pragma unroll
    for (int t = 0; t < 4; ++t) {
        int i = tid + t * THREADS;          // 1024 chunks: 64 rows x 16
        int r = i >> 4, ch = i & 15;
        uint32_t d = swzb(r, ch);
        const size_t off = (size_t)r * DD + ch * 8;
        CP16(dst + d,         khi + off);
        CP16(dst + 16384 + d, klo + off);
    }
}
__device__ __forceinline__ void issue_v(uint32_t dst, const __half* __restrict__ v, int tid) {
    #pragma unroll
    for (int t = 0; t < 4; ++t) {
        int i = tid + t * THREADS;
        int r = i >> 4, ch = i & 15;
        CP16(dst + swzb(r, ch), v + (size_t)r * DD + ch * 8);
    }
}

__global__ void __launch_bounds__(THREADS, 1)
Model_48876727828871_kernel(const float* __restrict__ Q, const float* __restrict__ SF,
                            float* __restrict__ O) {
    extern __shared__ char smem[];
    const uint32_t smb = smem_u32(smem);

    const int tid  = threadIdx.x;
    const int lane = tid & 31;
    const int w    = tid >> 5;
    const int qb   = blockIdx.x;
    const int b    = blockIdx.y;

    const size_t q_base  = ((size_t)b * LQ + (size_t)qb * BQ) * DD;
    const size_t kv_base = (size_t)b * LK * DD;
    const size_t sf_base = ((size_t)b * LQ + (size_t)qb * BQ) * LK;
    const __half* khi_b = g_khi + kv_base;
    const __half* klo_b = g_klo + kv_base;
    const __half* v_b   = g_v   + kv_base;

    // prologue: K0+V0 (group1), K1 (group2)
    issue_k(smb + SM_K,           khi_b,           klo_b,           tid);
    issue_v(smb + SM_V,           v_b,             tid);
    CPCOMMIT();
    issue_k(smb + SM_K + KBUF_SZ, khi_b + BK * DD, klo_b + BK * DD, tid);
    CPCOMMIT();

    // load + split Q tile
    #pragma unroll 4
    for (int i = tid; i < BQ * (DD / 4); i += THREADS) {
        int r  = i >> 5;
        int c4 = (i & 31) << 2;
        float4 x = *(const float4*)(Q + q_base + (size_t)r * DD + c4);
        uint32_t off = swzb(r, c4 >> 3) + (c4 & 4) * 2;
        split_store4h(x, (__half*)(smem + SM_QHI + off), (__half*)(smem + SM_QLO + off));
    }
    CPWAIT(1);                 // K0,V0 resident
    __syncthreads();

    // accumulators / state
    float o[16][4];
    #pragma unroll
    for (int n = 0; n < 16; ++n) { o[n][0]=0.f; o[n][1]=0.f; o[n][2]=0.f; o[n][3]=0.f; }
    float m0 = -1e30f, m1 = -1e30f, l0 = 0.f, l1 = 0.f;
    uint32_t pk[32];           // packed P (hi+lo) for 4 j-blocks
    float cfr[8][4];
    float2 s0[8], s1[8];

    const int wr = w * 16;
    const int g  = lane >> 2;
    const int qr = lane & 3;
    const int r0 = wr + g, r1 = r0 + 8;
    const uint32_t qh_b = smb + SM_QHI;
    const uint32_t ql_b = smb + SM_QLO;
    const float* sfp = SF + sf_base + (size_t)r0 * LK + qr * 2;

    // QK block macro: S(tile using kbuf `KB`) -> cfr
    #define QK_BLOCK(KB) do { \
        const uint32_t kh_b = (KB), kl_b = (KB) + 16384; \
        _Pragma("unroll") \
        for (int n = 0; n < 8; ++n) { cfr[n][0]=0.f; cfr[n][1]=0.f; cfr[n][2]=0.f; cfr[n][3]=0.f; } \
        _Pragma("unroll") \
        for (int kk = 0; kk < 8; ++kk) { \
            const uint32_t aoff = swzb(wr + (lane & 15), kk * 2 + (lane >> 4)); \
            uint32_t ah0,ah1,ah2,ah3, axl0,axl1,axl2,axl3; \
            ldsm_x4(ah0,ah1,ah2,ah3, qh_b + aoff); \
            ldsm_x4(axl0,axl1,axl2,axl3, ql_b + aoff); \
            _Pragma("unroll") \
            for (int np = 0; np < 4; ++np) { \
                const uint32_t boff = swzb(np * 16 + ((lane >> 4) & 1) * 8 + (lane & 7), \
                                           kk * 2 + ((lane >> 3) & 1)); \
                uint32_t bh0,bh1,bh2,bh3, bl0,bl1,bl2,bl3; \
                ldsm_x4(bh0,bh1,bh2,bh3, kh_b + boff); \
                ldsm_x4(bl0,bl1,bl2,bl3, kl_b + boff); \
                mma_f16(cfr[2*np],   ah0,ah1,ah2,ah3, bh0,bh1); \
                mma_f16(cfr[2*np+1], ah0,ah1,ah2,ah3, bh2,bh3); \
                mma_f16(cfr[2*np],   ah0,ah1,ah2,ah3, bl0,bl1); \
                mma_f16(cfr[2*np+1], ah0,ah1,ah2,ah3, bl2,bl3); \
                mma_f16(cfr[2*np],   axl0,axl1,axl2,axl3, bh0,bh1); \
                mma_f16(cfr[2*np+1], axl0,axl1,axl2,axl3, bh2,bh3); \
            } \
        } \
    } while (0)

    #define PV_STEP(j, np) do { \
        const int vrow = (j) * 16 + ((lane >> 3) & 1) * 8 + (lane & 7); \
        const int vch  = 2 * (np) + (lane >> 4); \
        uint32_t v0,v1,v2,v3; \
        ldsm_x4t(v0,v1,v2,v3, vb + swzb(vrow, vch)); \
        mma_f16(o[2*(np)],   pk[8*(j)+0],pk[8*(j)+1],pk[8*(j)+2],pk[8*(j)+3], v0,v1); \
        mma_f16(o[2*(np)+1], pk[8*(j)+0],pk[8*(j)+1],pk[8*(j)+2],pk[8*(j)+3], v2,v3); \
        mma_f16(o[2*(np)],   pk[8*(j)+4],pk[8*(j)+5],pk[8*(j)+6],pk[8*(j)+7], v0,v1); \
        mma_f16(o[2*(np)+1], pk[8*(j)+4],pk[8*(j)+5],pk[8*(j)+6],pk[8*(j)+7], v2,v3); \
    } while (0)

    #define SCALE_N(n) do { \
        cfr[n][0] *= s0[n].x; cfr[n][1] *= s0[n].y; \
        cfr[n][2] *= s1[n].x; cfr[n][3] *= s1[n].y; \
        mx0 = fmaxf(mx0, fmaxf(cfr[n][0], cfr[n][1])); \
        mx1 = fmaxf(mx1, fmaxf(cfr[n][2], cfr[n][3])); \
    } while (0)

    #define EXP_N(n) do { \
        cfr[n][0] = exp2f(cfr[n][0] * LOG2E - bb0); \
        cfr[n][1] = exp2f(cfr[n][1] * LOG2E - bb0); \
        cfr[n][2] = exp2f(cfr[n][2] * LOG2E - bb1); \
        cfr[n][3] = exp2f(cfr[n][3] * LOG2E - bb1); \
        rs0 += cfr[n][0] + cfr[n][1]; \
        rs1 += cfr[n][2] + cfr[n][3]; \
    } while (0)

    // prologue compute: SF(0) + QK(0)
    #pragma unroll
    for (int n = 0; n < 8; ++n) {
        s0[n] = __ldcs((const float2*)(sfp + n * 8));
        s1[n] = __ldcs((const float2*)(sfp + n * 8 + 8 * LK));
    }
    QK_BLOCK(smb + SM_K);
    __syncthreads();           // QK(0) reads done before iter0 writes kbuf0

    for (int kt = 0; kt < NKT; ++kt) {
        // ---- top prefetch: K(kt+2) -> kbuf[kt&1], V(kt+1) -> vbuf[(kt+1)%3] ----
        if (kt + 2 < NKT)
            issue_k(smb + SM_K + (kt & 1) * KBUF_SZ,
                    khi_b + (size_t)(kt + 2) * BK * DD, klo_b + (size_t)(kt + 2) * BK * DD, tid);
        if (kt + 1 < NKT)
            issue_v(smb + SM_V + ((kt + 1) % 3) * VBUF_SZ, v_b + (size_t)(kt + 1) * BK * DD, tid);
        CPCOMMIT();
        CPWAIT(1);             // K(kt+1) + V(kt-1..kt) drained
        __syncthreads();       // make all threads' async data visible

        // ---- block A: PV(kt-1) interleaved with softmax(kt) ----
        const uint32_t vb = smb + SM_V + ((kt + 2) % 3) * VBUF_SZ;   // (kt-1)%3
        float mx0 = -1e30f, mx1 = -1e30f, rs0 = 0.f, rs1 = 0.f;
        float al0, al1, bb0, bb1;

        if (kt > 0) { PV_STEP(0,0); PV_STEP(0,1); PV_STEP(0,2); PV_STEP(0,3); }
        SCALE_N(0); SCALE_N(1); SCALE_N(2); SCALE_N(3);
        if (kt > 0) { PV_STEP(0,4); PV_STEP(0,5); PV_STEP(0,6); PV_STEP(0,7); }
        SCALE_N(4); SCALE_N(5); SCALE_N(6); SCALE_N(7);
        if (kt > 0) { PV_STEP(1,0); PV_STEP(1,1); PV_STEP(1,2); PV_STEP(1,3); }
        {
            mx0 = fmaxf(mx0, __shfl_xor_sync(0xffffffffu, mx0, 1));
            mx0 = fmaxf(mx0, __shfl_xor_sync(0xffffffffu, mx0, 2));
            mx1 = fmaxf(mx1, __shfl_xor_sync(0xffffffffu, mx1, 1));
            mx1 = fmaxf(mx1, __shfl_xor_sync(0xffffffffu, mx1, 2));
            const float mn0 = fmaxf(m0, mx0), mn1 = fmaxf(m1, mx1);
            al0 = exp2f((m0 - mn0) * LOG2E);
            al1 = exp2f((m1 - mn1) * LOG2E);
            m0 = mn0; m1 = mn1;
            bb0 = m0 * LOG2E; bb1 = m1 * LOG2E;
        }
        if (kt > 0) { PV_STEP(1,4); PV_STEP(1,5); PV_STEP(1,6); PV_STEP(1,7); }
        EXP_N(0); EXP_N(1);
        if (kt > 0) { PV_STEP(2,0); PV_STEP(2,1); PV_STEP(2,2); PV_STEP(2,3); }
        EXP_N(2); EXP_N(3);
        if (kt > 0) { PV_STEP(2,4); PV_STEP(2,5); PV_STEP(2,6); PV_STEP(2,7); }
        EXP_N(4); EXP_N(5);
        if (kt > 0) { PV_STEP(3,0); PV_STEP(3,1); PV_STEP(3,2); PV_STEP(3,3); }
        EXP_N(6); EXP_N(7);
        if (kt > 0) { PV_STEP(3,4); PV_STEP(3,5); PV_STEP(3,6); PV_STEP(3,7); }
        {
            rs0 += __shfl_xor_sync(0xffffffffu, rs0, 1);
            rs0 += __shfl_xor_sync(0xffffffffu, rs0, 2);
            rs1 += __shfl_xor_sync(0xffffffffu, rs1, 1);
            rs1 += __shfl_xor_sync(0xffffffffu, rs1, 2);
            l0 = l0 * al0 + rs0;
            l1 = l1 * al1 + rs1;
        }

        // ---- block B: pack P(kt) -> pk; rescale o by alpha ----
        #pragma unroll
        for (int j = 0; j < 4; ++j) {
            #pragma unroll
            for (int c = 0; c < 4; ++c) {
                const float pa = cfr[2*j + (c >> 1)][(c & 1) * 2];
                const float pb = cfr[2*j + (c >> 1)][(c & 1) * 2 + 1];
                pk[8*j + c]     = packh(pa, pb);
                pk[8*j + 4 + c] = packh(pa - hif(pa), pb - hif(pb));
            }
        }
        #pragma unroll
        for (int n = 0; n < 16; ++n) {
            o[n][0] *= al0; o[n][1] *= al0;
            o[n][2] *= al1; o[n][3] *= al1;
        }

        // ---- block C: SF(kt+1) + QK(kt+1) ----
        if (kt + 1 < NKT) {
            #pragma unroll
            for (int n = 0; n < 8; ++n) {
                s0[n] = __ldcs((const float2*)(sfp + (size_t)(kt + 1) * BK + n * 8));
                s1[n] = __ldcs((const float2*)(sfp + (size_t)(kt + 1) * BK + n * 8 + 8 * LK));
            }
            QK_BLOCK(smb + SM_K + ((kt + 1) & 1) * KBUF_SZ);
        }
        __syncthreads();       // all reads of this iter done before next-iter writes
    }

    // ---- post-loop: PV(NKT-1) ----
    {
        const uint32_t vb = smb + SM_V + ((NKT - 1) % 3) * VBUF_SZ;
        #pragma unroll
        for (int j = 0; j < 4; ++j) {
            #pragma unroll
            for (int np = 0; np < 8; ++np) {
                PV_STEP(j, np);
            }
        }
    }

    // ---- epilogue ----
    const float inv0 = 1.f / l0;
    const float inv1 = 1.f / l1;
    #pragma unroll
    for (int n = 0; n < 16; ++n) {
        const int col = n * 8 + qr * 2;
        float2 t0; t0.x = o[n][0] * inv0; t0.y = o[n][1] * inv0;
        *(float2*)(O + q_base + (size_t)r0 * DD + col) = t0;
        float2 t1; t1.x = o[n][2] * inv1; t1.y = o[n][3] * inv1;
        *(float2*)(O + q_base + (size_t)r1 * DD + col) = t1;
    }
}

extern "C" void kernel_launch(void* const* d_in, const int* in_sizes, int n_in,
                              void* d_out, int out_size) {
    (void)in_sizes; (void)n_in; (void)out_size;
    const float* q  = (const float*)d_in[0];
    const float* k  = (const float*)d_in[1];
    const float* v  = (const float*)d_in[2];
    const float* sf = (const float*)d_in[3];
    float* out = (float*)d_out;

    prepass_kv<<<1024, 256>>>((const float4*)k, (const float4*)v);

    cudaFuncSetAttribute(Model_48876727828871_kernel,
                         cudaFuncAttributeMaxDynamicSharedMemorySize, SMEM_BYTES);
    dim3 grid(LQ / BQ, NB);
    Model_48876727828871_kernel<<<grid, THREADS, SMEM_BYTES>>>(q, sf, out);
}

// round 17
// speedup vs baseline: 2.5293x; 1.1015x over previous
#include <cuda_runtime.h>
#include <cuda_fp16.h>
#include <cstdint>

// Problem constants
#define NB   8
#define LQ   2048
#define LK   2048
#define DD   128
#define BQ   128
#define BK   64
#define THREADS 256            // 8 warps, each owns 16 Q rows
#define NKT  (LK / BK)
#define LOG2E 1.4426950408889634f

// SMEM map (bytes): 256B swizzled rows
#define SM_QHI   0             // 128x128 fp16 = 32768
#define SM_QLO   32768
#define SM_K     65536         // 3 K-buffers {khi,klo} 32KB each
#define KBUF_SZ  32768
#define SM_V     163840        // 3 V-buffers 16KB each
#define VBUF_SZ  16384
#define SMEM_BYTES 212992      // 64K Q + 96K K + 48K V

// Prepass scratch: K split fp16 hi/lo + V fp16 (24 MB)
__device__ __half g_khi[(size_t)NB * LK * DD];
__device__ __half g_klo[(size_t)NB * LK * DD];
__device__ __half g_v  [(size_t)NB * LK * DD];

__device__ __forceinline__ uint32_t smem_u32(const void* p) {
    return (uint32_t)__cvta_generic_to_shared(p);
}
// XOR swizzle: 256B rows, 16B chunks; low-3 chunk bits XOR row&7.
__device__ __forceinline__ uint32_t swzb(int row, int ch) {
    return (uint32_t)(row * 256 + ((((ch ^ row) & 7) | (ch & 8)) << 4));
}
__device__ __forceinline__ void ldsm_x4(uint32_t& r0, uint32_t& r1, uint32_t& r2, uint32_t& r3, uint32_t a) {
    asm volatile("ldmatrix.sync.aligned.m8n8.x4.shared.b16 {%0,%1,%2,%3}, [%4];\n"
        : "=r"(r0), "=r"(r1), "=r"(r2), "=r"(r3) : "r"(a));
}
__device__ __forceinline__ void ldsm_x4t(uint32_t& r0, uint32_t& r1, uint32_t& r2, uint32_t& r3, uint32_t a) {
    asm volatile("ldmatrix.sync.aligned.m8n8.x4.trans.shared.b16 {%0,%1,%2,%3}, [%4];\n"
        : "=r"(r0), "=r"(r1), "=r"(r2), "=r"(r3) : "r"(a));
}
__device__ __forceinline__ void mma_f16(float* c,
    uint32_t a0, uint32_t a1, uint32_t a2, uint32_t a3, uint32_t b0, uint32_t b1) {
    asm volatile(
      "mma.sync.aligned.m16n8k16.row.col.f32.f16.f16.f32 "
      "{%0,%1,%2,%3}, {%4,%5,%6,%7}, {%8,%9}, {%0,%1,%2,%3};\n"
      : "+f"(c[0]), "+f"(c[1]), "+f"(c[2]), "+f"(c[3])
      : "r"(a0), "r"(a1), "r"(a2), "r"(a3), "r"(b0), "r"(b1));
}
__device__ __forceinline__ uint32_t packh(float x, float y) {
    uint32_t r;
    asm("cvt.rn.f16x2.f32 %0, %1, %2;\n" : "=r"(r) : "f"(y), "f"(x));
    return r;
}
__device__ __forceinline__ float hif(float x) {
    return __half2float(__float2half_rn(x));
}
// single-MUFU exp2 (2 ulp, ftz) — the library exp2f is a multi-instr routine
__device__ __forceinline__ float ex2(float x) {
    float y; asm("ex2.approx.ftz.f32 %0, %1;\n" : "=f"(y) : "f"(x)); return y;
}
__device__ __forceinline__ void split_store4h(float4 x, __half* hi, __half* lo) {
    *(uint32_t*)(hi)     = packh(x.x, x.y);
    *(uint32_t*)(hi + 2) = packh(x.z, x.w);
    *(uint32_t*)(lo)     = packh(x.x - hif(x.x), x.y - hif(x.y));
    *(uint32_t*)(lo + 2) = packh(x.z - hif(x.z), x.w - hif(x.w));
}

#define CP16(dst, src) asm volatile("cp.async.cg.shared.global [%0], [%1], 16;\n" :: "r"(dst), "l"(src))
#define CPCOMMIT()     asm volatile("cp.async.commit_group;\n" ::: "memory")
#define CPWAIT(n)      asm volatile("cp.async.wait_group %0;\n" :: "n"(n) : "memory")

// ---- fused prepass: K -> fp16 hi/lo, V -> fp16 ----
__global__ void prepass_kv(const float4* __restrict__ K, const float4* __restrict__ V) {
    const int n4 = NB * LK * DD / 4;
    for (int i = blockIdx.x * blockDim.x + threadIdx.x; i < n4; i += gridDim.x * blockDim.x) {
        float4 xk = K[i];
        split_store4h(xk, g_khi + (size_t)i * 4, g_klo + (size_t)i * 4);
        float4 xv = V[i];
        uint2 p; p.x = packh(xv.x, xv.y); p.y = packh(xv.z, xv.w);
        *(uint2*)(g_v + (size_t)i * 4) = p;
    }
}

__device__ __forceinline__ void issue_k(uint32_t dst,
    const __half* __restrict__ khi, const __half* __restrict__ klo, int tid) {
    #pragma unroll
    for (int t = 0; t < 4; ++t) {
        int i = tid + t * THREADS;          // 1024 chunks: 64 rows x 16
        int r = i >> 4, ch = i & 15;
        uint32_t d = swzb(r, ch);
        const size_t off = (size_t)r * DD + ch * 8;
        CP16(dst + d,         khi + off);
        CP16(dst + 16384 + d, klo + off);
    }
}
__device__ __forceinline__ void issue_v(uint32_t dst, const __half* __restrict__ v, int tid) {
    #pragma unroll
    for (int t = 0; t < 4; ++t) {
        int i = tid + t * THREADS;
        int r = i >> 4, ch = i & 15;
        CP16(dst + swzb(r, ch), v + (size_t)r * DD + ch * 8);
    }
}

__global__ void __launch_bounds__(THREADS, 1)
Model_48876727828871_kernel(const float* __restrict__ Q, const float* __restrict__ SF,
                            float* __restrict__ O) {
    extern __shared__ char smem[];
    const uint32_t smb = smem_u32(smem);

    const int tid  = threadIdx.x;
    const int lane = tid & 31;
    const int w    = tid >> 5;
    const int qb   = blockIdx.x;
    const int b    = blockIdx.y;

    const size_t q_base  = ((size_t)b * LQ + (size_t)qb * BQ) * DD;
    const size_t kv_base = (size_t)b * LK * DD;
    const size_t sf_base = ((size_t)b * LQ + (size_t)qb * BQ) * LK;
    const __half* khi_b = g_khi + kv_base;
    const __half* klo_b = g_klo + kv_base;
    const __half* v_b   = g_v   + kv_base;

    // prologue groups: G1={K0,V0}, G2={K1}, G3={K2}
    issue_k(smb + SM_K,               khi_b,                klo_b,                tid);
    issue_v(smb + SM_V,               v_b,                  tid);
    CPCOMMIT();
    issue_k(smb + SM_K + KBUF_SZ,     khi_b +     BK * DD,  klo_b +     BK * DD,  tid);
    CPCOMMIT();
    issue_k(smb + SM_K + 2 * KBUF_SZ, khi_b + 2 * BK * DD,  klo_b + 2 * BK * DD,  tid);
    CPCOMMIT();

    // load + split Q tile
    #pragma unroll 4
    for (int i = tid; i < BQ * (DD / 4); i += THREADS) {
        int r  = i >> 5;
        int c4 = (i & 31) << 2;
        float4 x = *(const float4*)(Q + q_base + (size_t)r * DD + c4);
        uint32_t off = swzb(r, c4 >> 3) + (c4 & 4) * 2;
        split_store4h(x, (__half*)(smem + SM_QHI + off), (__half*)(smem + SM_QLO + off));
    }
    CPWAIT(2);                 // G1 drained: K0,V0 resident
    __syncthreads();

    // accumulators / state
    float o[16][4];
    #pragma unroll
    for (int n = 0; n < 16; ++n) { o[n][0]=0.f; o[n][1]=0.f; o[n][2]=0.f; o[n][3]=0.f; }
    float m0 = -1e30f, m1 = -1e30f, l0 = 0.f, l1 = 0.f;
    uint32_t pk[16];           // packed P (hi only) for 4 j-blocks
    float cfr[8][4];
    float2 s0[8], s1[8];

    const int wr = w * 16;
    const int g  = lane >> 2;
    const int qr = lane & 3;
    const int r0 = wr + g, r1 = r0 + 8;
    const uint32_t qh_b = smb + SM_QHI;
    const uint32_t ql_b = smb + SM_QLO;
    const float* sfp = SF + sf_base + (size_t)r0 * LK + qr * 2;

    // one kk-slice of QK (3-term), accumulating into all cfr[0..7]
    #define QK_KK(kk) do { \
        const uint32_t aoff = swzb(wr + (lane & 15), (kk) * 2 + (lane >> 4)); \
        uint32_t ah0,ah1,ah2,ah3, axl0,axl1,axl2,axl3; \
        ldsm_x4(ah0,ah1,ah2,ah3, qh_b + aoff); \
        ldsm_x4(axl0,axl1,axl2,axl3, ql_b + aoff); \
        _Pragma("unroll") \
        for (int np = 0; np < 4; ++np) { \
            const uint32_t boff = swzb(np * 16 + ((lane >> 4) & 1) * 8 + (lane & 7), \
                                       (kk) * 2 + ((lane >> 3) & 1)); \
            uint32_t bh0,bh1,bh2,bh3, bl0,bl1,bl2,bl3; \
            ldsm_x4(bh0,bh1,bh2,bh3, kh_b + boff); \
            ldsm_x4(bl0,bl1,bl2,bl3, kl_b + boff); \
            mma_f16(cfr[2*np],   ah0,ah1,ah2,ah3, bh0,bh1); \
            mma_f16(cfr[2*np+1], ah0,ah1,ah2,ah3, bh2,bh3); \
            mma_f16(cfr[2*np],   ah0,ah1,ah2,ah3, bl0,bl1); \
            mma_f16(cfr[2*np+1], ah0,ah1,ah2,ah3, bl2,bl3); \
            mma_f16(cfr[2*np],   axl0,axl1,axl2,axl3, bh0,bh1); \
            mma_f16(cfr[2*np+1], axl0,axl1,axl2,axl3, bh2,bh3); \
        } \
    } while (0)

    #define QK_ZERO() do { \
        _Pragma("unroll") \
        for (int n = 0; n < 8; ++n) { cfr[n][0]=0.f; cfr[n][1]=0.f; cfr[n][2]=0.f; cfr[n][3]=0.f; } \
    } while (0)

    // PV step: P hi only (2 MMAs)
    #define PV_STEP(j, np) do { \
        const int vrow = (j) * 16 + ((lane >> 3) & 1) * 8 + (lane & 7); \
        const int vch  = 2 * (np) + (lane >> 4); \
        uint32_t v0,v1,v2,v3; \
        ldsm_x4t(v0,v1,v2,v3, vb + swzb(vrow, vch)); \
        mma_f16(o[2*(np)],   pk[4*(j)+0],pk[4*(j)+1],pk[4*(j)+2],pk[4*(j)+3], v0,v1); \
        mma_f16(o[2*(np)+1], pk[4*(j)+0],pk[4*(j)+1],pk[4*(j)+2],pk[4*(j)+3], v2,v3); \
    } while (0)

    #define SCALE_N(n) do { \
        cfr[n][0] *= s0[n].x; cfr[n][1] *= s0[n].y; \
        cfr[n][2] *= s1[n].x; cfr[n][3] *= s1[n].y; \
        mx0 = fmaxf(mx0, fmaxf(cfr[n][0], cfr[n][1])); \
        mx1 = fmaxf(mx1, fmaxf(cfr[n][2], cfr[n][3])); \
    } while (0)

    #define EXP_N(n) do { \
        cfr[n][0] = ex2(cfr[n][0] * LOG2E - bb0); \
        cfr[n][1] = ex2(cfr[n][1] * LOG2E - bb0); \
        cfr[n][2] = ex2(cfr[n][2] * LOG2E - bb1); \
        cfr[n][3] = ex2(cfr[n][3] * LOG2E - bb1); \
        rs0 += cfr[n][0] + cfr[n][1]; \
        rs1 += cfr[n][2] + cfr[n][3]; \
    } while (0)

    #define PACK_ALL() do { \
        _Pragma("unroll") \
        for (int j = 0; j < 4; ++j) { \
            _Pragma("unroll") \
            for (int c = 0; c < 4; ++c) { \
                const float pa = cfr[2*j + (c >> 1)][(c & 1) * 2]; \
                const float pb = cfr[2*j + (c >> 1)][(c & 1) * 2 + 1]; \
                pk[4*j + c] = packh(pa, pb); \
            } \
        } \
    } while (0)

    #define RESC_N(n) do { \
        o[n][0] *= al0; o[n][1] *= al0; o[n][2] *= al1; o[n][3] *= al1; \
    } while (0)

    // prologue compute: SF(0) + QK(0)
    #pragma unroll
    for (int n = 0; n < 8; ++n) {
        s0[n] = __ldcs((const float2*)(sfp + n * 8));
        s1[n] = __ldcs((const float2*)(sfp + n * 8 + 8 * LK));
    }
    {
        const uint32_t kh_b = smb + SM_K, kl_b = kh_b + 16384;
        QK_ZERO();
        QK_KK(0); QK_KK(1); QK_KK(2); QK_KK(3);
        QK_KK(4); QK_KK(5); QK_KK(6); QK_KK(7);
    }

    for (int kt = 0; kt < NKT; ++kt) {
        // ---- barrier FIRST (drains K(kt+1), V(kt-1); fences prior-iter reads),
        //      THEN issue prefetches into now-safe buffers ----
        CPWAIT(1);
        __syncthreads();
        if (kt + 3 < NKT)
            issue_k(smb + SM_K + (kt % 3) * KBUF_SZ,
                    khi_b + (size_t)(kt + 3) * BK * DD, klo_b + (size_t)(kt + 3) * BK * DD, tid);
        if (kt + 1 < NKT)
            issue_v(smb + SM_V + ((kt + 1) % 3) * VBUF_SZ, v_b + (size_t)(kt + 1) * BK * DD, tid);
        CPCOMMIT();

        // ---- block A: PV(kt-1) (hi only) interleaved with softmax(kt) ----
        const uint32_t vb = smb + SM_V + ((kt + 2) % 3) * VBUF_SZ;   // (kt-1)%3
        float mx0 = -1e30f, mx1 = -1e30f, rs0 = 0.f, rs1 = 0.f;
        float al0, al1, bb0, bb1;

        if (kt > 0) { PV_STEP(0,0); PV_STEP(0,1); PV_STEP(0,2); PV_STEP(0,3); }
        SCALE_N(0); SCALE_N(1); SCALE_N(2); SCALE_N(3);
        if (kt > 0) { PV_STEP(0,4); PV_STEP(0,5); PV_STEP(0,6); PV_STEP(0,7); }
        SCALE_N(4); SCALE_N(5); SCALE_N(6); SCALE_N(7);
        if (kt > 0) { PV_STEP(1,0); PV_STEP(1,1); PV_STEP(1,2); PV_STEP(1,3); }
        {
            mx0 = fmaxf(mx0, __shfl_xor_sync(0xffffffffu, mx0, 1));
            mx0 = fmaxf(mx0, __shfl_xor_sync(0xffffffffu, mx0, 2));
            mx1 = fmaxf(mx1, __shfl_xor_sync(0xffffffffu, mx1, 1));
            mx1 = fmaxf(mx1, __shfl_xor_sync(0xffffffffu, mx1, 2));
            const float mn0 = fmaxf(m0, mx0), mn1 = fmaxf(m1, mx1);
            al0 = ex2((m0 - mn0) * LOG2E);
            al1 = ex2((m1 - mn1) * LOG2E);
            m0 = mn0; m1 = mn1;
            bb0 = m0 * LOG2E; bb1 = m1 * LOG2E;
        }
        if (kt > 0) { PV_STEP(1,4); PV_STEP(1,5); PV_STEP(1,6); PV_STEP(1,7); }
        EXP_N(0); EXP_N(1);
        if (kt > 0) { PV_STEP(2,0); PV_STEP(2,1); PV_STEP(2,2); PV_STEP(2,3); }
        EXP_N(2); EXP_N(3);
        if (kt > 0) { PV_STEP(2,4); PV_STEP(2,5); PV_STEP(2,6); PV_STEP(2,7); }
        EXP_N(4); EXP_N(5);
        if (kt > 0) { PV_STEP(3,0); PV_STEP(3,1); PV_STEP(3,2); PV_STEP(3,3); }
        EXP_N(6); EXP_N(7);
        if (kt > 0) { PV_STEP(3,4); PV_STEP(3,5); PV_STEP(3,6); PV_STEP(3,7); }
        {
            rs0 += __shfl_xor_sync(0xffffffffu, rs0, 1);
            rs0 += __shfl_xor_sync(0xffffffffu, rs0, 2);
            rs1 += __shfl_xor_sync(0xffffffffu, rs1, 1);
            rs1 += __shfl_xor_sync(0xffffffffu, rs1, 2);
            l0 = l0 * al0 + rs0;
            l1 = l1 * al1 + rs1;
        }

        // ---- block B/C: pack P(kt); QK(kt+1) interleaved with o-rescale ----
        PACK_ALL();
        if (kt + 1 < NKT) {
            #pragma unroll
            for (int n = 0; n < 8; ++n) {
                s0[n] = __ldcs((const float2*)(sfp + (size_t)(kt + 1) * BK + n * 8));
                s1[n] = __ldcs((const float2*)(sfp + (size_t)(kt + 1) * BK + n * 8 + 8 * LK));
            }
            const uint32_t kh_b = smb + SM_K + ((kt + 1) % 3) * KBUF_SZ, kl_b = kh_b + 16384;
            QK_ZERO();
            QK_KK(0); RESC_N(0);  RESC_N(1);
            QK_KK(1); RESC_N(2);  RESC_N(3);
            QK_KK(2); RESC_N(4);  RESC_N(5);
            QK_KK(3); RESC_N(6);  RESC_N(7);
            QK_KK(4); RESC_N(8);  RESC_N(9);
            QK_KK(5); RESC_N(10); RESC_N(11);
            QK_KK(6); RESC_N(12); RESC_N(13);
            QK_KK(7); RESC_N(14); RESC_N(15);
        } else {
            #pragma unroll
            for (int n = 0; n < 16; ++n) { RESC_N(n); }
        }
    }

    // ---- post-loop: PV(NKT-1) ----
    {
        const uint32_t vb = smb + SM_V + ((NKT - 1) % 3) * VBUF_SZ;
        #pragma unroll
        for (int j = 0; j < 4; ++j) {
            #pragma unroll
            for (int np = 0; np < 8; ++np) {
                PV_STEP(j, np);
            }
        }
    }

    // ---- epilogue ----
    const float inv0 = 1.f / l0;
    const float inv1 = 1.f / l1;
    #pragma unroll
    for (int n = 0; n < 16; ++n) {
        const int col = n * 8 + qr * 2;
        float2 t0; t0.x = o[n][0] * inv0; t0.y = o[n][1] * inv0;
        *(float2*)(O + q_base + (size_t)r0 * DD + col) = t0;
        float2 t1; t1.x = o[n][2] * inv1; t1.y = o[n][3] * inv1;
        *(float2*)(O + q_base + (size_t)r1 * DD + col) = t1;
    }
}

extern "C" void kernel_launch(void* const* d_in, const int* in_sizes, int n_in,
                              void* d_out, int out_size) {
    (void)in_sizes; (void)n_in; (void)out_size;
    const float* q  = (const float*)d_in[0];
    const float* k  = (const float*)d_in[1];
    const float* v  = (const float*)d_in[2];
    const float* sf = (const float*)d_in[3];
    float* out = (float*)d_out;

    prepass_kv<<<1024, 256>>>((const float4*)k, (const float4*)v);

    cudaFuncSetAttribute(Model_48876727828871_kernel,
                         cudaFuncAttributeMaxDynamicSharedMemorySize, SMEM_BYTES);
    dim3 grid(LQ / BQ, NB);
    Model_48876727828871_kernel<<<grid, THREADS, SMEM_BYTES>>>(q, sf, out);
}